// round 1
// baseline (speedup 1.0000x reference)
#include <cuda_runtime.h>
#include <math.h>

// Problem constants
#define BB   64
#define TT   256
#define DD   1024
#define HH   16
#define DH   64
#define BT   (BB*TT)      // 16384
#define HB   (HH*BB)      // 1024
#define TS   (TT*TT)      // 65536

#define NEG_BIG_F (-4294967296.0f)  // float32 rounding of -2^32+1, matches jnp cast

// Scratch (allocation-free rule: __device__ globals)
__device__ float g_temporal[BT * DD];          // 64 MB
__device__ float g_q[BT * DD];                 // 64 MB
__device__ float g_k[BT * DD];                 // 64 MB
__device__ float g_v[BT * DD];                 // 64 MB
__device__ float g_scores[(size_t)HB * TS];    // 256 MB (scores -> probs in-place)

// ---------------------------------------------------------------------------
// Kernel 1: temporal = x + pos_emb (broadcast over batch), float4 vectorized
// ---------------------------------------------------------------------------
__global__ void add_pos_kernel(const float* __restrict__ x,
                               const float* __restrict__ pos,
                               float* __restrict__ out) {
    int i4 = blockIdx.x * blockDim.x + threadIdx.x;   // float4 index
    int n4 = BT * DD / 4;
    if (i4 >= n4) return;
    int td4 = i4 % (TT * DD / 4);                     // position within one batch row-block
    float4 xv = ((const float4*)x)[i4];
    float4 pv = ((const float4*)pos)[td4];
    xv.x += pv.x; xv.y += pv.y; xv.z += pv.z; xv.w += pv.w;
    ((float4*)out)[i4] = xv;
}

// ---------------------------------------------------------------------------
// Kernel 2: SGEMM  C[M,N] = A[M,K] * W[K,N],  M=16384, N=1024, K=1024
// 128x128 block tile, BK=8, 256 threads, 8x8 per-thread tile
// ---------------------------------------------------------------------------
__global__ __launch_bounds__(256) void sgemm128_kernel(const float* __restrict__ A,
                                                       const float* __restrict__ W,
                                                       float* __restrict__ C) {
    const int N = DD, K = DD;
    __shared__ float As[8][128];
    __shared__ float Bs[8][128];

    const int tid  = threadIdx.x;
    const int brow = blockIdx.y * 128;
    const int bcol = blockIdx.x * 128;
    const int trow = (tid / 16) * 8;
    const int tcol = (tid % 16) * 8;

    const int arow = tid / 2;
    const int acol = (tid % 2) * 4;
    const int wrow = tid / 32;
    const int wcol = (tid % 32) * 4;

    const float* Aptr = A + (size_t)(brow + arow) * K + acol;
    const float* Wptr = W + (size_t)wrow * N + bcol + wcol;

    float acc[8][8];
#pragma unroll
    for (int i = 0; i < 8; i++)
#pragma unroll
        for (int j = 0; j < 8; j++) acc[i][j] = 0.0f;

    for (int k0 = 0; k0 < K; k0 += 8) {
        float4 a = *(const float4*)(Aptr + k0);
        As[acol + 0][arow] = a.x;
        As[acol + 1][arow] = a.y;
        As[acol + 2][arow] = a.z;
        As[acol + 3][arow] = a.w;
        float4 w = *(const float4*)(Wptr + (size_t)k0 * N);
        *(float4*)&Bs[wrow][wcol] = w;
        __syncthreads();

#pragma unroll
        for (int k = 0; k < 8; k++) {
            float4 m0 = *(const float4*)&As[k][trow];
            float4 m1 = *(const float4*)&As[k][trow + 4];
            float4 n0 = *(const float4*)&Bs[k][tcol];
            float4 n1 = *(const float4*)&Bs[k][tcol + 4];
            float rm[8] = {m0.x, m0.y, m0.z, m0.w, m1.x, m1.y, m1.z, m1.w};
            float rn[8] = {n0.x, n0.y, n0.z, n0.w, n1.x, n1.y, n1.z, n1.w};
#pragma unroll
            for (int i = 0; i < 8; i++)
#pragma unroll
                for (int j = 0; j < 8; j++) acc[i][j] = fmaf(rm[i], rn[j], acc[i][j]);
        }
        __syncthreads();
    }

#pragma unroll
    for (int i = 0; i < 8; i++) {
        float* Cp = C + (size_t)(brow + trow + i) * N + bcol + tcol;
        *(float4*)(Cp + 0) = make_float4(acc[i][0], acc[i][1], acc[i][2], acc[i][3]);
        *(float4*)(Cp + 4) = make_float4(acc[i][4], acc[i][5], acc[i][6], acc[i][7]);
    }
}

// ---------------------------------------------------------------------------
// Kernel 3: scores[bh][t][s] = (q_.k_)/16 with lower-tri (s<=t) -> NEG_BIG
// Block: 64t x 64s tile for one bh. q_[h*B+b,t,:] = q[b,t,h*64:...]
// ---------------------------------------------------------------------------
__global__ __launch_bounds__(256) void scores_kernel(const float* __restrict__ q,
                                                     const float* __restrict__ k,
                                                     float* __restrict__ scores) {
    const int bh = blockIdx.z;
    const int b = bh & (BB - 1);
    const int h = bh >> 6;
    const int t0 = blockIdx.y * 64;
    const int s0 = blockIdx.x * 64;

    __shared__ float Qs[64][65];
    __shared__ float Ks[64][65];

    const int tid = threadIdx.x;
    const float* qbase = q + ((size_t)(b * TT + t0)) * DD + h * DH;
    const float* kbase = k + ((size_t)(b * TT + s0)) * DD + h * DH;

#pragma unroll
    for (int i = 0; i < 4; i++) {
        int idx = tid + i * 256;        // 0..1023 float4 slots
        int r = idx >> 4;
        int c = (idx & 15) * 4;
        float4 qv = *(const float4*)(qbase + (size_t)r * DD + c);
        Qs[r][c] = qv.x; Qs[r][c + 1] = qv.y; Qs[r][c + 2] = qv.z; Qs[r][c + 3] = qv.w;
        float4 kv = *(const float4*)(kbase + (size_t)r * DD + c);
        Ks[r][c] = kv.x; Ks[r][c + 1] = kv.y; Ks[r][c + 2] = kv.z; Ks[r][c + 3] = kv.w;
    }
    __syncthreads();

    const int trow = (tid / 16) * 4;
    const int tcol = (tid % 16) * 4;
    float acc[4][4];
#pragma unroll
    for (int i = 0; i < 4; i++)
#pragma unroll
        for (int j = 0; j < 4; j++) acc[i][j] = 0.0f;

#pragma unroll 8
    for (int kk = 0; kk < 64; kk++) {
        float rq[4], rk[4];
#pragma unroll
        for (int i = 0; i < 4; i++) rq[i] = Qs[trow + i][kk];
#pragma unroll
        for (int j = 0; j < 4; j++) rk[j] = Ks[tcol + j][kk];
#pragma unroll
        for (int i = 0; i < 4; i++)
#pragma unroll
            for (int j = 0; j < 4; j++) acc[i][j] = fmaf(rq[i], rk[j], acc[i][j]);
    }

    float* out = scores + (size_t)bh * TS;
#pragma unroll
    for (int i = 0; i < 4; i++) {
        int t = t0 + trow + i;
#pragma unroll
        for (int j = 0; j < 4; j++) {
            int s = s0 + tcol + j;
            float val = (s <= t) ? NEG_BIG_F : acc[i][j] * (1.0f / 16.0f);
            out[t * TT + s] = val;
        }
    }
}

// ---------------------------------------------------------------------------
// Kernel 4: softmax over the bh axis (axis 0). One thread per (t,s).
// scores layout [bh][t][s] -> per-iteration warp reads are contiguous in s.
// Masked columns (all values == NEG_BIG) naturally give uniform 1/1024.
// ---------------------------------------------------------------------------
__global__ void softmax_bh_kernel(float* __restrict__ scores) {
    int ts = blockIdx.x * blockDim.x + threadIdx.x;
    if (ts >= TS) return;
    float* p = scores + ts;

    float m = -INFINITY;
#pragma unroll 8
    for (int bh = 0; bh < HB; bh++) m = fmaxf(m, p[bh * TS]);

    float sum = 0.0f;
#pragma unroll 8
    for (int bh = 0; bh < HB; bh++) sum += __expf(p[bh * TS] - m);

    float inv = 1.0f / sum;
#pragma unroll 8
    for (int bh = 0; bh < HB; bh++) p[bh * TS] = __expf(p[bh * TS] - m) * inv;
}

// ---------------------------------------------------------------------------
// Kernel 5: out[bh,t,:] = probs[bh,t,:] @ v_[bh,:,:]; merge heads on store.
// Block: one bh, 64-row t tile, full dh=64 width. K loop over s (256).
// ---------------------------------------------------------------------------
__global__ __launch_bounds__(256) void out_kernel(const float* __restrict__ probs,
                                                  const float* __restrict__ v,
                                                  float* __restrict__ out) {
    const int bh = blockIdx.y;
    const int b = bh & (BB - 1);
    const int h = bh >> 6;
    const int t0 = blockIdx.x * 64;

    __shared__ float Ps[64][65];   // [t][s-chunk]
    __shared__ float Vs[64][65];   // [s][d]

    const int tid = threadIdx.x;
    const float* pbase = probs + (size_t)bh * TS + t0 * TT;
    const float* vbase = v + (size_t)b * TT * DD + h * DH;

    const int trow = (tid / 16) * 4;
    const int tcol = (tid % 16) * 4;
    float acc[4][4];
#pragma unroll
    for (int i = 0; i < 4; i++)
#pragma unroll
        for (int j = 0; j < 4; j++) acc[i][j] = 0.0f;

    for (int s0 = 0; s0 < TT; s0 += 64) {
#pragma unroll
        for (int i = 0; i < 4; i++) {
            int idx = tid + i * 256;
            int r = idx >> 4;
            int c = (idx & 15) * 4;
            float4 pv = *(const float4*)(pbase + (size_t)r * TT + s0 + c);
            Ps[r][c] = pv.x; Ps[r][c + 1] = pv.y; Ps[r][c + 2] = pv.z; Ps[r][c + 3] = pv.w;
            float4 vv = *(const float4*)(vbase + (size_t)(s0 + r) * DD + c);
            Vs[r][c] = vv.x; Vs[r][c + 1] = vv.y; Vs[r][c + 2] = vv.z; Vs[r][c + 3] = vv.w;
        }
        __syncthreads();

#pragma unroll 8
        for (int kk = 0; kk < 64; kk++) {
            float rp[4], rv[4];
#pragma unroll
            for (int i = 0; i < 4; i++) rp[i] = Ps[trow + i][kk];
#pragma unroll
            for (int j = 0; j < 4; j++) rv[j] = Vs[kk][tcol + j];
#pragma unroll
            for (int i = 0; i < 4; i++)
#pragma unroll
                for (int j = 0; j < 4; j++) acc[i][j] = fmaf(rp[i], rv[j], acc[i][j]);
        }
        __syncthreads();
    }

    float* obase = out + (size_t)(b * TT + t0) * DD + h * DH;
#pragma unroll
    for (int i = 0; i < 4; i++) {
        float* op = obase + (size_t)(trow + i) * DD + tcol;
        *(float4*)op = make_float4(acc[i][0], acc[i][1], acc[i][2], acc[i][3]);
    }
}

// ---------------------------------------------------------------------------
// Launch
// ---------------------------------------------------------------------------
extern "C" void kernel_launch(void* const* d_in, const int* in_sizes, int n_in,
                              void* d_out, int out_size) {
    const float* x   = (const float*)d_in[0];
    const float* pos = (const float*)d_in[1];
    const float* Wq  = (const float*)d_in[2];
    const float* Wk  = (const float*)d_in[3];
    const float* Wv  = (const float*)d_in[4];
    float* out = (float*)d_out;

    float* temporal; cudaGetSymbolAddress((void**)&temporal, g_temporal);
    float* q;        cudaGetSymbolAddress((void**)&q, g_q);
    float* k;        cudaGetSymbolAddress((void**)&k, g_k);
    float* v;        cudaGetSymbolAddress((void**)&v, g_v);
    float* scores;   cudaGetSymbolAddress((void**)&scores, g_scores);

    // 1. temporal = x + pos_emb
    {
        int n4 = BT * DD / 4;
        add_pos_kernel<<<(n4 + 255) / 256, 256>>>(x, pos, temporal);
    }

    // 2. q/k/v projections
    {
        dim3 grid(DD / 128, BT / 128);
        sgemm128_kernel<<<grid, 256>>>(temporal, Wq, q);
        sgemm128_kernel<<<grid, 256>>>(temporal, Wk, k);
        sgemm128_kernel<<<grid, 256>>>(temporal, Wv, v);
    }

    // 3. masked scaled scores
    {
        dim3 grid(TT / 64, TT / 64, HB);
        scores_kernel<<<grid, 256>>>(q, k, scores);
    }

    // 4. softmax over bh axis (in-place -> probs)
    softmax_bh_kernel<<<TS / 256, 256>>>(scores);

    // 5. probs @ v_, heads merged on store
    {
        dim3 grid(TT / 64, HB);
        out_kernel<<<grid, 256>>>(scores, v, out);
    }
}

// round 3
// speedup vs baseline: 1.9527x; 1.9527x over previous
#include <cuda_runtime.h>
#include <cuda_bf16.h>
#include <math.h>
#include <stdint.h>

// Problem constants
#define BB   64
#define TT   256
#define DD   1024
#define HH   16
#define DH   64
#define BT   (BB*TT)      // 16384
#define HB   (HH*BB)      // 1024
#define TS   (TT*TT)      // 65536

#define NEG_BIG_F (-4294967296.0f)

// ---------------------------------------------------------------------------
// Scratch (__device__ globals; no allocation allowed)
// ---------------------------------------------------------------------------
__device__ __nv_bfloat16 g_ahi[BT * DD];        // 32 MB
__device__ __nv_bfloat16 g_alo[BT * DD];        // 32 MB
__device__ __nv_bfloat16 g_wthi[3][DD * DD];    // 2 MB x3  (transposed: [n][k])
__device__ __nv_bfloat16 g_wtlo[3][DD * DD];    // 2 MB x3
__device__ float g_q[BT * DD];                  // 64 MB
__device__ float g_k[BT * DD];                  // 64 MB
__device__ float g_v[BT * DD];                  // 64 MB
__device__ float g_scores[(size_t)HB * TS];     // 256 MB

// ---------------------------------------------------------------------------
// helpers
// ---------------------------------------------------------------------------
__device__ __forceinline__ uint32_t smem_u32(const void* p) {
    uint32_t a;
    asm("{ .reg .u64 t; cvta.to.shared.u64 t, %1; cvt.u32.u64 %0, t; }" : "=r"(a) : "l"(p));
    return a;
}
__device__ __forceinline__ void ldsm4(uint32_t* r, uint32_t a) {
    asm volatile("ldmatrix.sync.aligned.m8n8.x4.shared.b16 {%0,%1,%2,%3}, [%4];"
                 : "=r"(r[0]), "=r"(r[1]), "=r"(r[2]), "=r"(r[3]) : "r"(a));
}
__device__ __forceinline__ void mma16816(float* c, const uint32_t* a, const uint32_t* b) {
    asm volatile(
        "mma.sync.aligned.m16n8k16.row.col.f32.bf16.bf16.f32 "
        "{%0,%1,%2,%3}, {%4,%5,%6,%7}, {%8,%9}, {%0,%1,%2,%3};"
        : "+f"(c[0]), "+f"(c[1]), "+f"(c[2]), "+f"(c[3])
        : "r"(a[0]), "r"(a[1]), "r"(a[2]), "r"(a[3]), "r"(b[0]), "r"(b[1]));
}
#define CP16(sa, gp) \
    asm volatile("cp.async.ca.shared.global [%0], [%1], 16;" :: "r"(sa), "l"(gp))
#define CP_COMMIT() asm volatile("cp.async.commit_group;" ::: "memory")
#define CP_WAIT(n)  asm volatile("cp.async.wait_group %0;" :: "n"(n) : "memory")

// ---------------------------------------------------------------------------
// Kernel 1: (x + pos) -> split into bf16 hi/lo
// ---------------------------------------------------------------------------
__global__ void add_split_kernel(const float* __restrict__ x,
                                 const float* __restrict__ pos,
                                 __nv_bfloat16* __restrict__ ahi,
                                 __nv_bfloat16* __restrict__ alo) {
    int i4 = blockIdx.x * blockDim.x + threadIdx.x;
    int n4 = BT * DD / 4;
    if (i4 >= n4) return;
    int td4 = i4 % (TT * DD / 4);
    float4 xv = ((const float4*)x)[i4];
    float4 pv = ((const float4*)pos)[td4];
    float a[4] = {xv.x + pv.x, xv.y + pv.y, xv.z + pv.z, xv.w + pv.w};
    __nv_bfloat16 hi[4], lo[4];
#pragma unroll
    for (int j = 0; j < 4; j++) {
        hi[j] = __float2bfloat16_rn(a[j]);
        lo[j] = __float2bfloat16_rn(a[j] - __bfloat162float(hi[j]));
    }
    __nv_bfloat162 h0; h0.x = hi[0]; h0.y = hi[1];
    __nv_bfloat162 h1; h1.x = hi[2]; h1.y = hi[3];
    __nv_bfloat162 l0; l0.x = lo[0]; l0.y = lo[1];
    __nv_bfloat162 l1; l1.x = lo[2]; l1.y = lo[3];
    ((__nv_bfloat162*)ahi)[i4 * 2 + 0] = h0;
    ((__nv_bfloat162*)ahi)[i4 * 2 + 1] = h1;
    ((__nv_bfloat162*)alo)[i4 * 2 + 0] = l0;
    ((__nv_bfloat162*)alo)[i4 * 2 + 1] = l1;
}

// ---------------------------------------------------------------------------
// Kernel 2: weight transpose + split:  Wt_hi/lo[n][k] = split(W[k][n])
// ---------------------------------------------------------------------------
__global__ void wsplit_kernel(const float* __restrict__ W,
                              __nv_bfloat16* __restrict__ thi,
                              __nv_bfloat16* __restrict__ tlo) {
    __shared__ float tile[32][33];
    int k0 = blockIdx.x * 32;
    int n0 = blockIdx.y * 32;
    int tx = threadIdx.x;
    int ty = threadIdx.y;
#pragma unroll
    for (int i = 0; i < 32; i += 8)
        tile[ty + i][tx] = W[(size_t)(k0 + ty + i) * DD + n0 + tx];
    __syncthreads();
#pragma unroll
    for (int i = 0; i < 32; i += 8) {
        float v = tile[tx][ty + i];
        __nv_bfloat16 hi = __float2bfloat16_rn(v);
        __nv_bfloat16 lo = __float2bfloat16_rn(v - __bfloat162float(hi));
        thi[(size_t)(n0 + ty + i) * DD + k0 + tx] = hi;
        tlo[(size_t)(n0 + ty + i) * DD + k0 + tx] = lo;
    }
}

// ---------------------------------------------------------------------------
// Kernel 3: HMMA (mma.sync bf16, split 3-product) GEMM
// C[16384,1024] = A * W   (W passed transposed [n][k])
// 128x128 CTA tile, BK=32, 512 threads (4x4 warps, 32x32 warp tile),
// cp.async double-buffered, ldmatrix fragments, fp32 accum.
// ---------------------------------------------------------------------------
#define G_BM 128
#define G_BN 128
#define G_BK 32
#define G_NCH (DD / G_BK)        // 32
#define G_RS 40                   // smem row stride (halfs) -> 80 B, conflict-free
#define G_TILE_B (128 * G_RS * 2) // 10240 B per tile
#define OFF_AHI 0
#define OFF_ALO (1 * G_TILE_B)
#define OFF_BHI (2 * G_TILE_B)
#define OFF_BLO (3 * G_TILE_B)
#define G_STAGE (4 * G_TILE_B)    // 40960
#define GEMM_SMEM (2 * G_STAGE)   // 81920

__global__ __launch_bounds__(512) void gemm_hmma_kernel(
    const __nv_bfloat16* __restrict__ Ahi, const __nv_bfloat16* __restrict__ Alo,
    const __nv_bfloat16* __restrict__ Bhi, const __nv_bfloat16* __restrict__ Blo,
    float* __restrict__ C)
{
    extern __shared__ char smem[];
    const uint32_t sb = smem_u32(smem);
    const int tid = threadIdx.x;
    const int lane = tid & 31;
    const int wid = tid >> 5;
    const int wm = wid & 3;        // warp row 0..3
    const int wn = wid >> 2;       // warp col 0..3
    const int brow = blockIdx.y * G_BM;
    const int bcol = blockIdx.x * G_BN;

    // gmem->smem copy indices (one 16B segment per thread per tile)
    const int crow = tid >> 2;           // 0..127
    const int cseg = tid & 3;            // 0..3 (8 halfs each)
    const uint32_t s_off = (uint32_t)(crow * (G_RS * 2) + cseg * 16);
    const size_t ga_base = (size_t)(brow + crow) * DD + cseg * 8;
    const size_t gb_base = (size_t)(bcol + crow) * DD + cseg * 8;

    // ldmatrix lane addressing
    const int a_row = lane & 15;
    const int a_k8  = (lane >> 4) * 8;              // 0 or 8 halfs
    const int b_row = (lane & 7) + ((lane & 16) ? 8 : 0);
    const int b_k8  = (lane & 8) ? 8 : 0;

    float acc[2][4][4];
#pragma unroll
    for (int mt = 0; mt < 2; mt++)
#pragma unroll
        for (int nt = 0; nt < 4; nt++)
#pragma unroll
            for (int i = 0; i < 4; i++) acc[mt][nt][i] = 0.0f;

    // prefetch chunk 0
    {
        uint32_t st = sb + s_off;
        CP16(st + OFF_AHI, Ahi + ga_base);
        CP16(st + OFF_ALO, Alo + ga_base);
        CP16(st + OFF_BHI, Bhi + gb_base);
        CP16(st + OFF_BLO, Blo + gb_base);
        CP_COMMIT();
    }

    for (int ch = 0; ch < G_NCH; ch++) {
        if (ch + 1 < G_NCH) {
            uint32_t st = sb + ((ch + 1) & 1) * G_STAGE + s_off;
            size_t goff = (size_t)(ch + 1) * G_BK;
            CP16(st + OFF_AHI, Ahi + ga_base + goff);
            CP16(st + OFF_ALO, Alo + ga_base + goff);
            CP16(st + OFF_BHI, Bhi + gb_base + goff);
            CP16(st + OFF_BLO, Blo + gb_base + goff);
            CP_COMMIT();
            CP_WAIT(1);
        } else {
            CP_WAIT(0);
        }
        __syncthreads();

        const uint32_t st = sb + (ch & 1) * G_STAGE;
#pragma unroll
        for (int ks = 0; ks < 2; ks++) {
            uint32_t aH[2][4], aL[2][4];
#pragma unroll
            for (int mt = 0; mt < 2; mt++) {
                uint32_t ao = st + (uint32_t)((wm * 32 + mt * 16 + a_row) * (G_RS * 2) +
                                              (ks * 16 + a_k8) * 2);
                ldsm4(aH[mt], ao + OFF_AHI);
                ldsm4(aL[mt], ao + OFF_ALO);
            }
            uint32_t bH[2][4], bL[2][4];
#pragma unroll
            for (int p = 0; p < 2; p++) {
                uint32_t bo = st + (uint32_t)((wn * 32 + p * 16 + b_row) * (G_RS * 2) +
                                              (ks * 16 + b_k8) * 2);
                ldsm4(bH[p], bo + OFF_BHI);
                ldsm4(bL[p], bo + OFF_BLO);
            }
#pragma unroll
            for (int mt = 0; mt < 2; mt++)
#pragma unroll
                for (int nt = 0; nt < 4; nt++) {
                    const uint32_t* bh = &bH[nt >> 1][(nt & 1) * 2];
                    const uint32_t* bl = &bL[nt >> 1][(nt & 1) * 2];
                    mma16816(acc[mt][nt], aH[mt], bh);
                    mma16816(acc[mt][nt], aH[mt], bl);
                    mma16816(acc[mt][nt], aL[mt], bh);
                }
        }
        __syncthreads();
    }

    // epilogue: c0,c1 at (row, col..col+1); c2,c3 at (row+8, ...)
#pragma unroll
    for (int mt = 0; mt < 2; mt++) {
        int row = brow + wm * 32 + mt * 16 + (lane >> 2);
#pragma unroll
        for (int nt = 0; nt < 4; nt++) {
            int col = bcol + wn * 32 + nt * 8 + (lane & 3) * 2;
            *(float2*)(C + (size_t)row * DD + col) =
                make_float2(acc[mt][nt][0], acc[mt][nt][1]);
            *(float2*)(C + (size_t)(row + 8) * DD + col) =
                make_float2(acc[mt][nt][2], acc[mt][nt][3]);
        }
    }
}

// ---------------------------------------------------------------------------
// Kernel 4: scores[bh][t][s] = (q.k)/16 for s>t only.
// Tiles fully below the diagonal (s0 < t0) are skipped entirely; masked
// entries are never stored (softmax writes them without reading).
// ---------------------------------------------------------------------------
__global__ __launch_bounds__(256) void scores_kernel(const float* __restrict__ q,
                                                     const float* __restrict__ k,
                                                     float* __restrict__ scores) {
    const int t0 = blockIdx.y * 64;
    const int s0 = blockIdx.x * 64;
    if (s0 < t0) return;   // fully masked tile

    const int bh = blockIdx.z;
    const int b = bh & (BB - 1);
    const int h = bh >> 6;

    __shared__ float Qs[64][65];
    __shared__ float Ks[64][65];

    const int tid = threadIdx.x;
    const float* qbase = q + ((size_t)(b * TT + t0)) * DD + h * DH;
    const float* kbase = k + ((size_t)(b * TT + s0)) * DD + h * DH;

#pragma unroll
    for (int i = 0; i < 4; i++) {
        int idx = tid + i * 256;
        int r = idx >> 4;
        int c = (idx & 15) * 4;
        float4 qv = *(const float4*)(qbase + (size_t)r * DD + c);
        Qs[r][c] = qv.x; Qs[r][c + 1] = qv.y; Qs[r][c + 2] = qv.z; Qs[r][c + 3] = qv.w;
        float4 kv = *(const float4*)(kbase + (size_t)r * DD + c);
        Ks[r][c] = kv.x; Ks[r][c + 1] = kv.y; Ks[r][c + 2] = kv.z; Ks[r][c + 3] = kv.w;
    }
    __syncthreads();

    const int trow = (tid / 16) * 4;
    const int tcol = (tid % 16) * 4;
    float acc[4][4];
#pragma unroll
    for (int i = 0; i < 4; i++)
#pragma unroll
        for (int j = 0; j < 4; j++) acc[i][j] = 0.0f;

#pragma unroll 8
    for (int kk = 0; kk < 64; kk++) {
        float rq[4], rk[4];
#pragma unroll
        for (int i = 0; i < 4; i++) rq[i] = Qs[trow + i][kk];
#pragma unroll
        for (int j = 0; j < 4; j++) rk[j] = Ks[tcol + j][kk];
#pragma unroll
        for (int i = 0; i < 4; i++)
#pragma unroll
            for (int j = 0; j < 4; j++) acc[i][j] = fmaf(rq[i], rk[j], acc[i][j]);
    }

    float* out = scores + (size_t)bh * TS;
#pragma unroll
    for (int i = 0; i < 4; i++) {
        int t = t0 + trow + i;
#pragma unroll
        for (int j = 0; j < 4; j++) {
            int s = s0 + tcol + j;
            if (s > t) out[t * TT + s] = acc[i][j] * (1.0f / 16.0f);
        }
    }
}

// ---------------------------------------------------------------------------
// Kernel 5: softmax over the bh axis. Masked (s<=t) columns are exactly
// uniform 1/1024 -> write-only fast path, no reads.
// ---------------------------------------------------------------------------
__global__ void softmax_bh_kernel(float* __restrict__ scores) {
    int ts = blockIdx.x * blockDim.x + threadIdx.x;
    if (ts >= TS) return;
    int t = ts >> 8;
    int s = ts & 255;
    float* p = scores + ts;

    if (s <= t) {
        const float u = 1.0f / 1024.0f;
#pragma unroll 8
        for (int bh = 0; bh < HB; bh++) p[bh * TS] = u;
        return;
    }

    float m = -INFINITY;
#pragma unroll 8
    for (int bh = 0; bh < HB; bh++) m = fmaxf(m, p[bh * TS]);

    float sum = 0.0f;
#pragma unroll 8
    for (int bh = 0; bh < HB; bh++) sum += __expf(p[bh * TS] - m);

    float inv = 1.0f / sum;
#pragma unroll 8
    for (int bh = 0; bh < HB; bh++) p[bh * TS] = __expf(p[bh * TS] - m) * inv;
}

// ---------------------------------------------------------------------------
// Kernel 6: out[bh,t,:] = probs[bh,t,:] @ v_[bh,:,:]; merge heads on store.
// ---------------------------------------------------------------------------
__global__ __launch_bounds__(256) void out_kernel(const float* __restrict__ probs,
                                                  const float* __restrict__ v,
                                                  float* __restrict__ out) {
    const int bh = blockIdx.y;
    const int b = bh & (BB - 1);
    const int h = bh >> 6;
    const int t0 = blockIdx.x * 64;

    __shared__ float Ps[64][65];
    __shared__ float Vs[64][65];

    const int tid = threadIdx.x;
    const float* pbase = probs + (size_t)bh * TS + t0 * TT;
    const float* vbase = v + (size_t)b * TT * DD + h * DH;

    const int trow = (tid / 16) * 4;
    const int tcol = (tid % 16) * 4;
    float acc[4][4];
#pragma unroll
    for (int i = 0; i < 4; i++)
#pragma unroll
        for (int j = 0; j < 4; j++) acc[i][j] = 0.0f;

    for (int s0 = 0; s0 < TT; s0 += 64) {
#pragma unroll
        for (int i = 0; i < 4; i++) {
            int idx = tid + i * 256;
            int r = idx >> 4;
            int c = (idx & 15) * 4;
            float4 pv = *(const float4*)(pbase + (size_t)r * TT + s0 + c);
            Ps[r][c] = pv.x; Ps[r][c + 1] = pv.y; Ps[r][c + 2] = pv.z; Ps[r][c + 3] = pv.w;
            float4 vv = *(const float4*)(vbase + (size_t)(s0 + r) * DD + c);
            Vs[r][c] = vv.x; Vs[r][c + 1] = vv.y; Vs[r][c + 2] = vv.z; Vs[r][c + 3] = vv.w;
        }
        __syncthreads();

#pragma unroll 8
        for (int kk = 0; kk < 64; kk++) {
            float rp[4], rv[4];
#pragma unroll
            for (int i = 0; i < 4; i++) rp[i] = Ps[trow + i][kk];
#pragma unroll
            for (int j = 0; j < 4; j++) rv[j] = Vs[kk][tcol + j];
#pragma unroll
            for (int i = 0; i < 4; i++)
#pragma unroll
                for (int j = 0; j < 4; j++) acc[i][j] = fmaf(rp[i], rv[j], acc[i][j]);
        }
        __syncthreads();
    }

    float* obase = out + (size_t)(b * TT + t0) * DD + h * DH;
#pragma unroll
    for (int i = 0; i < 4; i++) {
        float* op = obase + (size_t)(trow + i) * DD + tcol;
        *(float4*)op = make_float4(acc[i][0], acc[i][1], acc[i][2], acc[i][3]);
    }
}

// ---------------------------------------------------------------------------
// Launch
// ---------------------------------------------------------------------------
extern "C" void kernel_launch(void* const* d_in, const int* in_sizes, int n_in,
                              void* d_out, int out_size) {
    const float* x   = (const float*)d_in[0];
    const float* pos = (const float*)d_in[1];
    const float* W[3] = {(const float*)d_in[2], (const float*)d_in[3], (const float*)d_in[4]};
    float* out = (float*)d_out;

    __nv_bfloat16 *ahi, *alo, *wthi, *wtlo;
    float *q, *k, *v, *scores;
    cudaGetSymbolAddress((void**)&ahi, g_ahi);
    cudaGetSymbolAddress((void**)&alo, g_alo);
    cudaGetSymbolAddress((void**)&wthi, g_wthi);
    cudaGetSymbolAddress((void**)&wtlo, g_wtlo);
    cudaGetSymbolAddress((void**)&q, g_q);
    cudaGetSymbolAddress((void**)&k, g_k);
    cudaGetSymbolAddress((void**)&v, g_v);
    cudaGetSymbolAddress((void**)&scores, g_scores);

    cudaFuncSetAttribute(gemm_hmma_kernel,
                         cudaFuncAttributeMaxDynamicSharedMemorySize, GEMM_SMEM);

    // 1. (x + pos) -> bf16 hi/lo split
    {
        int n4 = BT * DD / 4;
        add_split_kernel<<<(n4 + 255) / 256, 256>>>(x, pos, ahi, alo);
    }

    // 2. weight transpose + split (x3)
    {
        dim3 blk(32, 8);
        dim3 grid(DD / 32, DD / 32);
        for (int i = 0; i < 3; i++)
            wsplit_kernel<<<grid, blk>>>(W[i], wthi + (size_t)i * DD * DD,
                                         wtlo + (size_t)i * DD * DD);
    }

    // 3. q/k/v projections on HMMA tensor cores (split-bf16, fp32 accumulate)
    {
        dim3 grid(DD / G_BN, BT / G_BM);   // (8, 128)
        float* outs[3] = {q, k, v};
        for (int i = 0; i < 3; i++)
            gemm_hmma_kernel<<<grid, 512, GEMM_SMEM>>>(
                ahi, alo,
                wthi + (size_t)i * DD * DD, wtlo + (size_t)i * DD * DD,
                outs[i]);
    }

    // 4. masked scaled scores (upper-triangular tiles only)
    {
        dim3 grid(TT / 64, TT / 64, HB);
        scores_kernel<<<grid, 256>>>(q, k, scores);
    }

    // 5. softmax over bh axis (in-place -> probs; masked cols write-only)
    softmax_bh_kernel<<<TS / 256, 256>>>(scores);

    // 6. probs @ v_, heads merged on store
    {
        dim3 grid(TT / 64, HB);
        out_kernel<<<grid, 256>>>(scores, v, out);
    }
}

// round 4
// speedup vs baseline: 2.2019x; 1.1276x over previous
#include <cuda_runtime.h>
#include <cuda_bf16.h>
#include <math.h>
#include <stdint.h>

// Problem constants
#define BB   64
#define TT   256
#define DD   1024
#define HH   16
#define DH   64
#define BT   (BB*TT)      // 16384
#define HB   (HH*BB)      // 1024
#define TS   (TT*TT)      // 65536

#define UNIF (1.0f / 1024.0f)

// ---------------------------------------------------------------------------
// Scratch (__device__ globals; no allocation allowed)
// ---------------------------------------------------------------------------
__device__ __nv_bfloat16 g_ahi[BT * DD];        // 32 MB
__device__ __nv_bfloat16 g_alo[BT * DD];        // 32 MB
__device__ __nv_bfloat16 g_wthi[3][DD * DD];    // 2 MB x3  (transposed: [n][k])
__device__ __nv_bfloat16 g_wtlo[3][DD * DD];    // 2 MB x3
__device__ float g_q[BT * DD];                  // 64 MB
__device__ float g_k[BT * DD];                  // 64 MB
__device__ float g_v[BT * DD];                  // 64 MB
__device__ float g_scores[(size_t)HB * TS];     // 256 MB (raw scores, s>t only)
__device__ float g_inv[TS];                     // 256 KB (1/sum per (t,s))

// ---------------------------------------------------------------------------
// helpers
// ---------------------------------------------------------------------------
__device__ __forceinline__ uint32_t smem_u32(const void* p) {
    uint32_t a;
    asm("{ .reg .u64 t; cvta.to.shared.u64 t, %1; cvt.u32.u64 %0, t; }" : "=r"(a) : "l"(p));
    return a;
}
__device__ __forceinline__ void ldsm4(uint32_t* r, uint32_t a) {
    asm volatile("ldmatrix.sync.aligned.m8n8.x4.shared.b16 {%0,%1,%2,%3}, [%4];"
                 : "=r"(r[0]), "=r"(r[1]), "=r"(r[2]), "=r"(r[3]) : "r"(a));
}
__device__ __forceinline__ void mma16816(float* c, const uint32_t* a, const uint32_t* b) {
    asm volatile(
        "mma.sync.aligned.m16n8k16.row.col.f32.bf16.bf16.f32 "
        "{%0,%1,%2,%3}, {%4,%5,%6,%7}, {%8,%9}, {%0,%1,%2,%3};"
        : "+f"(c[0]), "+f"(c[1]), "+f"(c[2]), "+f"(c[3])
        : "r"(a[0]), "r"(a[1]), "r"(a[2]), "r"(a[3]), "r"(b[0]), "r"(b[1]));
}
#define CP16(sa, gp) \
    asm volatile("cp.async.ca.shared.global [%0], [%1], 16;" :: "r"(sa), "l"(gp))
#define CP_COMMIT() asm volatile("cp.async.commit_group;" ::: "memory")
#define CP_WAIT(n)  asm volatile("cp.async.wait_group %0;" :: "n"(n) : "memory")

// ---------------------------------------------------------------------------
// Kernel 1: (x + pos) -> split into bf16 hi/lo
// ---------------------------------------------------------------------------
__global__ void add_split_kernel(const float* __restrict__ x,
                                 const float* __restrict__ pos,
                                 __nv_bfloat16* __restrict__ ahi,
                                 __nv_bfloat16* __restrict__ alo) {
    int i4 = blockIdx.x * blockDim.x + threadIdx.x;
    int n4 = BT * DD / 4;
    if (i4 >= n4) return;
    int td4 = i4 % (TT * DD / 4);
    float4 xv = ((const float4*)x)[i4];
    float4 pv = ((const float4*)pos)[td4];
    float a[4] = {xv.x + pv.x, xv.y + pv.y, xv.z + pv.z, xv.w + pv.w};
    __nv_bfloat16 hi[4], lo[4];
#pragma unroll
    for (int j = 0; j < 4; j++) {
        hi[j] = __float2bfloat16_rn(a[j]);
        lo[j] = __float2bfloat16_rn(a[j] - __bfloat162float(hi[j]));
    }
    __nv_bfloat162 h0; h0.x = hi[0]; h0.y = hi[1];
    __nv_bfloat162 h1; h1.x = hi[2]; h1.y = hi[3];
    __nv_bfloat162 l0; l0.x = lo[0]; l0.y = lo[1];
    __nv_bfloat162 l1; l1.x = lo[2]; l1.y = lo[3];
    ((__nv_bfloat162*)ahi)[i4 * 2 + 0] = h0;
    ((__nv_bfloat162*)ahi)[i4 * 2 + 1] = h1;
    ((__nv_bfloat162*)alo)[i4 * 2 + 0] = l0;
    ((__nv_bfloat162*)alo)[i4 * 2 + 1] = l1;
}

// ---------------------------------------------------------------------------
// Kernel 2: weight transpose + split:  Wt_hi/lo[n][k] = split(W[k][n])
// ---------------------------------------------------------------------------
__global__ void wsplit_kernel(const float* __restrict__ W,
                              __nv_bfloat16* __restrict__ thi,
                              __nv_bfloat16* __restrict__ tlo) {
    __shared__ float tile[32][33];
    int k0 = blockIdx.x * 32;
    int n0 = blockIdx.y * 32;
    int tx = threadIdx.x;
    int ty = threadIdx.y;
#pragma unroll
    for (int i = 0; i < 32; i += 8)
        tile[ty + i][tx] = W[(size_t)(k0 + ty + i) * DD + n0 + tx];
    __syncthreads();
#pragma unroll
    for (int i = 0; i < 32; i += 8) {
        float v = tile[tx][ty + i];
        __nv_bfloat16 hi = __float2bfloat16_rn(v);
        __nv_bfloat16 lo = __float2bfloat16_rn(v - __bfloat162float(hi));
        thi[(size_t)(n0 + ty + i) * DD + k0 + tx] = hi;
        tlo[(size_t)(n0 + ty + i) * DD + k0 + tx] = lo;
    }
}

// ---------------------------------------------------------------------------
// Kernel 3: HMMA (mma.sync bf16, split 3-product) GEMM
// ---------------------------------------------------------------------------
#define G_BM 128
#define G_BN 128
#define G_BK 32
#define G_NCH (DD / G_BK)        // 32
#define G_RS 40                   // smem row stride (halfs) -> 80 B
#define G_TILE_B (128 * G_RS * 2)
#define OFF_AHI 0
#define OFF_ALO (1 * G_TILE_B)
#define OFF_BHI (2 * G_TILE_B)
#define OFF_BLO (3 * G_TILE_B)
#define G_STAGE (4 * G_TILE_B)    // 40960
#define GEMM_SMEM (2 * G_STAGE)   // 81920

__global__ __launch_bounds__(512) void gemm_hmma_kernel(
    const __nv_bfloat16* __restrict__ Ahi, const __nv_bfloat16* __restrict__ Alo,
    const __nv_bfloat16* __restrict__ Bhi, const __nv_bfloat16* __restrict__ Blo,
    float* __restrict__ C)
{
    extern __shared__ char smem[];
    const uint32_t sb = smem_u32(smem);
    const int tid = threadIdx.x;
    const int lane = tid & 31;
    const int wid = tid >> 5;
    const int wm = wid & 3;
    const int wn = wid >> 2;
    const int brow = blockIdx.y * G_BM;
    const int bcol = blockIdx.x * G_BN;

    const int crow = tid >> 2;
    const int cseg = tid & 3;
    const uint32_t s_off = (uint32_t)(crow * (G_RS * 2) + cseg * 16);
    const size_t ga_base = (size_t)(brow + crow) * DD + cseg * 8;
    const size_t gb_base = (size_t)(bcol + crow) * DD + cseg * 8;

    const int a_row = lane & 15;
    const int a_k8  = (lane >> 4) * 8;
    const int b_row = (lane & 7) + ((lane & 16) ? 8 : 0);
    const int b_k8  = (lane & 8) ? 8 : 0;

    float acc[2][4][4];
#pragma unroll
    for (int mt = 0; mt < 2; mt++)
#pragma unroll
        for (int nt = 0; nt < 4; nt++)
#pragma unroll
            for (int i = 0; i < 4; i++) acc[mt][nt][i] = 0.0f;

    {
        uint32_t st = sb + s_off;
        CP16(st + OFF_AHI, Ahi + ga_base);
        CP16(st + OFF_ALO, Alo + ga_base);
        CP16(st + OFF_BHI, Bhi + gb_base);
        CP16(st + OFF_BLO, Blo + gb_base);
        CP_COMMIT();
    }

    for (int ch = 0; ch < G_NCH; ch++) {
        if (ch + 1 < G_NCH) {
            uint32_t st = sb + ((ch + 1) & 1) * G_STAGE + s_off;
            size_t goff = (size_t)(ch + 1) * G_BK;
            CP16(st + OFF_AHI, Ahi + ga_base + goff);
            CP16(st + OFF_ALO, Alo + ga_base + goff);
            CP16(st + OFF_BHI, Bhi + gb_base + goff);
            CP16(st + OFF_BLO, Blo + gb_base + goff);
            CP_COMMIT();
            CP_WAIT(1);
        } else {
            CP_WAIT(0);
        }
        __syncthreads();

        const uint32_t st = sb + (ch & 1) * G_STAGE;
#pragma unroll
        for (int ks = 0; ks < 2; ks++) {
            uint32_t aH[2][4], aL[2][4];
#pragma unroll
            for (int mt = 0; mt < 2; mt++) {
                uint32_t ao = st + (uint32_t)((wm * 32 + mt * 16 + a_row) * (G_RS * 2) +
                                              (ks * 16 + a_k8) * 2);
                ldsm4(aH[mt], ao + OFF_AHI);
                ldsm4(aL[mt], ao + OFF_ALO);
            }
            uint32_t bH[2][4], bL[2][4];
#pragma unroll
            for (int p = 0; p < 2; p++) {
                uint32_t bo = st + (uint32_t)((wn * 32 + p * 16 + b_row) * (G_RS * 2) +
                                              (ks * 16 + b_k8) * 2);
                ldsm4(bH[p], bo + OFF_BHI);
                ldsm4(bL[p], bo + OFF_BLO);
            }
#pragma unroll
            for (int mt = 0; mt < 2; mt++)
#pragma unroll
                for (int nt = 0; nt < 4; nt++) {
                    const uint32_t* bh = &bH[nt >> 1][(nt & 1) * 2];
                    const uint32_t* bl = &bL[nt >> 1][(nt & 1) * 2];
                    mma16816(acc[mt][nt], aH[mt], bh);
                    mma16816(acc[mt][nt], aH[mt], bl);
                    mma16816(acc[mt][nt], aL[mt], bh);
                }
        }
        __syncthreads();
    }

#pragma unroll
    for (int mt = 0; mt < 2; mt++) {
        int row = brow + wm * 32 + mt * 16 + (lane >> 2);
#pragma unroll
        for (int nt = 0; nt < 4; nt++) {
            int col = bcol + wn * 32 + nt * 8 + (lane & 3) * 2;
            *(float2*)(C + (size_t)row * DD + col) =
                make_float2(acc[mt][nt][0], acc[mt][nt][1]);
            *(float2*)(C + (size_t)(row + 8) * DD + col) =
                make_float2(acc[mt][nt][2], acc[mt][nt][3]);
        }
    }
}

// ---------------------------------------------------------------------------
// Kernel 4: scores[bh][t][s] = (q.k)/16 for s>t only (raw, unnormalized).
// ---------------------------------------------------------------------------
__global__ __launch_bounds__(256) void scores_kernel(const float* __restrict__ q,
                                                     const float* __restrict__ k,
                                                     float* __restrict__ scores) {
    const int t0 = blockIdx.y * 64;
    const int s0 = blockIdx.x * 64;
    if (s0 < t0) return;   // fully masked tile

    const int bh = blockIdx.z;
    const int b = bh & (BB - 1);
    const int h = bh >> 6;

    __shared__ float Qs[64][65];
    __shared__ float Ks[64][65];

    const int tid = threadIdx.x;
    const float* qbase = q + ((size_t)(b * TT + t0)) * DD + h * DH;
    const float* kbase = k + ((size_t)(b * TT + s0)) * DD + h * DH;

#pragma unroll
    for (int i = 0; i < 4; i++) {
        int idx = tid + i * 256;
        int r = idx >> 4;
        int c = (idx & 15) * 4;
        float4 qv = *(const float4*)(qbase + (size_t)r * DD + c);
        Qs[r][c] = qv.x; Qs[r][c + 1] = qv.y; Qs[r][c + 2] = qv.z; Qs[r][c + 3] = qv.w;
        float4 kv = *(const float4*)(kbase + (size_t)r * DD + c);
        Ks[r][c] = kv.x; Ks[r][c + 1] = kv.y; Ks[r][c + 2] = kv.z; Ks[r][c + 3] = kv.w;
    }
    __syncthreads();

    const int trow = (tid / 16) * 4;
    const int tcol = (tid % 16) * 4;
    float acc[4][4];
#pragma unroll
    for (int i = 0; i < 4; i++)
#pragma unroll
        for (int j = 0; j < 4; j++) acc[i][j] = 0.0f;

#pragma unroll 8
    for (int kk = 0; kk < 64; kk++) {
        float rq[4], rk[4];
#pragma unroll
        for (int i = 0; i < 4; i++) rq[i] = Qs[trow + i][kk];
#pragma unroll
        for (int j = 0; j < 4; j++) rk[j] = Ks[tcol + j][kk];
#pragma unroll
        for (int i = 0; i < 4; i++)
#pragma unroll
            for (int j = 0; j < 4; j++) acc[i][j] = fmaf(rq[i], rk[j], acc[i][j]);
    }

    float* out = scores + (size_t)bh * TS;
#pragma unroll
    for (int i = 0; i < 4; i++) {
        int t = t0 + trow + i;
#pragma unroll
        for (int j = 0; j < 4; j++) {
            int s = s0 + tcol + j;
            if (s > t) out[t * TT + s] = acc[i][j] * (1.0f / 16.0f);
        }
    }
}

// ---------------------------------------------------------------------------
// Kernel 5: expsum over the bh axis. Only unmasked (s>t) columns.
// inv[t][s] = 1 / sum_bh exp(score[bh][t][s]).   (max-free: |score| << 88)
// ---------------------------------------------------------------------------
__global__ void expsum_kernel(const float* __restrict__ scores,
                              float* __restrict__ inv) {
    int ts = blockIdx.x * blockDim.x + threadIdx.x;
    if (ts >= TS) return;
    int t = ts >> 8;
    int s = ts & 255;
    if (s <= t) return;
    const float* p = scores + ts;
    float sum = 0.0f;
#pragma unroll 8
    for (int bh = 0; bh < HB; bh++) sum += __expf(p[bh * TS]);
    inv[ts] = 1.0f / sum;
}

// ---------------------------------------------------------------------------
// Kernel 6: out[bh,t,:] = sum_s probs * v_[bh,s,:]
//   fully-masked s-tiles -> uniform 1/1024 * V column-sum  (rank-1, cheap)
//   diagonal tile        -> per-element weight (u or exp*inv)
//   upper tiles          -> exp(score)*inv on-the-fly, normal GEMM
// ---------------------------------------------------------------------------
__global__ __launch_bounds__(256) void out_kernel(const float* __restrict__ scores,
                                                  const float* __restrict__ inv,
                                                  const float* __restrict__ v,
                                                  float* __restrict__ out) {
    const int bh = blockIdx.y;
    const int b = bh & (BB - 1);
    const int h = bh >> 6;
    const int t0 = blockIdx.x * 64;

    __shared__ float Ps[64][65];
    __shared__ float Vs[64][65];

    const int tid = threadIdx.x;
    const float* sbase = scores + (size_t)bh * TS;
    const float* vbase = v + (size_t)b * TT * DD + h * DH;

    const int trow = (tid / 16) * 4;
    const int tcol = (tid % 16) * 4;
    float acc[4][4];
    float cs[4] = {0.0f, 0.0f, 0.0f, 0.0f};
#pragma unroll
    for (int i = 0; i < 4; i++)
#pragma unroll
        for (int j = 0; j < 4; j++) acc[i][j] = 0.0f;

    for (int s0 = 0; s0 < TT; s0 += 64) {
        const bool full_masked = (s0 + 64 <= t0);
        // load V tile always
#pragma unroll
        for (int i = 0; i < 4; i++) {
            int idx = tid + i * 256;
            int r = idx >> 4;
            int c = (idx & 15) * 4;
            float4 vv = *(const float4*)(vbase + (size_t)(s0 + r) * DD + c);
            Vs[r][c] = vv.x; Vs[r][c + 1] = vv.y; Vs[r][c + 2] = vv.z; Vs[r][c + 3] = vv.w;
        }
        if (!full_masked) {
            // fill Ps with final prob weights
#pragma unroll
            for (int i = 0; i < 4; i++) {
                int idx = tid + i * 256;
                int r = idx >> 6;          // 0..15 rows per pass? -> need 64 rows total
                // 1024 elements / 256 threads: 4 per thread, layout r = idx>>4? use same as V
            }
            // (re-done below with scalar loads; see loop)
#pragma unroll
            for (int i = 0; i < 4; i++) {
                int idx = tid + i * 256;
                int r = idx >> 4;          // 0..63
                int c4 = (idx & 15) * 4;   // 0..60
#pragma unroll
                for (int j = 0; j < 4; j++) {
                    int t = t0 + r;
                    int s = s0 + c4 + j;
                    float w;
                    if (s <= t) {
                        w = UNIF;
                    } else {
                        w = __expf(sbase[t * TT + s]) * inv[t * TT + s];
                    }
                    Ps[r][c4 + j] = w;
                }
            }
        }
        __syncthreads();

        if (full_masked) {
#pragma unroll 8
            for (int kk = 0; kk < 64; kk++) {
#pragma unroll
                for (int j = 0; j < 4; j++) cs[j] += Vs[kk][tcol + j];
            }
        } else {
#pragma unroll 8
            for (int kk = 0; kk < 64; kk++) {
                float rp[4], rv[4];
#pragma unroll
                for (int i = 0; i < 4; i++) rp[i] = Ps[trow + i][kk];
#pragma unroll
                for (int j = 0; j < 4; j++) rv[j] = Vs[kk][tcol + j];
#pragma unroll
                for (int i = 0; i < 4; i++)
#pragma unroll
                    for (int j = 0; j < 4; j++) acc[i][j] = fmaf(rp[i], rv[j], acc[i][j]);
            }
        }
        __syncthreads();
    }

    float* obase = out + (size_t)(b * TT + t0) * DD + h * DH;
#pragma unroll
    for (int i = 0; i < 4; i++) {
        float* op = obase + (size_t)(trow + i) * DD + tcol;
        *(float4*)op = make_float4(acc[i][0] + UNIF * cs[0],
                                   acc[i][1] + UNIF * cs[1],
                                   acc[i][2] + UNIF * cs[2],
                                   acc[i][3] + UNIF * cs[3]);
    }
}

// ---------------------------------------------------------------------------
// Launch
// ---------------------------------------------------------------------------
extern "C" void kernel_launch(void* const* d_in, const int* in_sizes, int n_in,
                              void* d_out, int out_size) {
    const float* x   = (const float*)d_in[0];
    const float* pos = (const float*)d_in[1];
    const float* W[3] = {(const float*)d_in[2], (const float*)d_in[3], (const float*)d_in[4]};
    float* out = (float*)d_out;

    __nv_bfloat16 *ahi, *alo, *wthi, *wtlo;
    float *q, *k, *v, *scores, *inv;
    cudaGetSymbolAddress((void**)&ahi, g_ahi);
    cudaGetSymbolAddress((void**)&alo, g_alo);
    cudaGetSymbolAddress((void**)&wthi, g_wthi);
    cudaGetSymbolAddress((void**)&wtlo, g_wtlo);
    cudaGetSymbolAddress((void**)&q, g_q);
    cudaGetSymbolAddress((void**)&k, g_k);
    cudaGetSymbolAddress((void**)&v, g_v);
    cudaGetSymbolAddress((void**)&scores, g_scores);
    cudaGetSymbolAddress((void**)&inv, g_inv);

    cudaFuncSetAttribute(gemm_hmma_kernel,
                         cudaFuncAttributeMaxDynamicSharedMemorySize, GEMM_SMEM);

    // 1. (x + pos) -> bf16 hi/lo split
    {
        int n4 = BT * DD / 4;
        add_split_kernel<<<(n4 + 255) / 256, 256>>>(x, pos, ahi, alo);
    }

    // 2. weight transpose + split (x3)
    {
        dim3 blk(32, 8);
        dim3 grid(DD / 32, DD / 32);
        for (int i = 0; i < 3; i++)
            wsplit_kernel<<<grid, blk>>>(W[i], wthi + (size_t)i * DD * DD,
                                         wtlo + (size_t)i * DD * DD);
    }

    // 3. q/k/v projections on HMMA tensor cores (split-bf16, fp32 accumulate)
    {
        dim3 grid(DD / G_BN, BT / G_BM);
        float* outs[3] = {q, k, v};
        for (int i = 0; i < 3; i++)
            gemm_hmma_kernel<<<grid, 512, GEMM_SMEM>>>(
                ahi, alo,
                wthi + (size_t)i * DD * DD, wtlo + (size_t)i * DD * DD,
                outs[i]);
    }

    // 4. raw masked scores (upper-triangular tiles only)
    {
        dim3 grid(TT / 64, TT / 64, HB);
        scores_kernel<<<grid, 256>>>(q, k, scores);
    }

    // 5. per-(t,s) exp-sum over bh -> inv (unmasked columns only)
    expsum_kernel<<<TS / 256, 256>>>(scores, inv);

    // 6. output: exp*inv on the fly; masked region via uniform * V-colsum
    {
        dim3 grid(TT / 64, HB);
        out_kernel<<<grid, 256>>>(scores, inv, v, out);
    }
}

// round 5
// speedup vs baseline: 2.3822x; 1.0819x over previous
#include <cuda_runtime.h>
#include <cuda_bf16.h>
#include <math.h>
#include <stdint.h>

// Problem constants
#define BB   64
#define TT   256
#define DD   1024
#define HH   16
#define DH   64
#define BT   (BB*TT)      // 16384
#define HB   (HH*BB)      // 1024
#define TS   (TT*TT)      // 65536

#define UNIF (1.0f / 1024.0f)

// ---------------------------------------------------------------------------
// Scratch (__device__ globals; no allocation allowed)
// ---------------------------------------------------------------------------
__device__ __nv_bfloat16 g_ahi[BT * DD];        // 32 MB
__device__ __nv_bfloat16 g_alo[BT * DD];        // 32 MB
__device__ __nv_bfloat16 g_wthi[3][DD * DD];    // 2 MB x3  (transposed: [n][k])
__device__ __nv_bfloat16 g_wtlo[3][DD * DD];    // 2 MB x3
__device__ __nv_bfloat16 g_qhi[BT * DD];        // 32 MB
__device__ __nv_bfloat16 g_qlo[BT * DD];        // 32 MB
__device__ __nv_bfloat16 g_khi[BT * DD];        // 32 MB
__device__ __nv_bfloat16 g_klo[BT * DD];        // 32 MB
__device__ float g_v[BT * DD];                  // 64 MB
__device__ float g_scores[(size_t)HB * TS];     // 256 MB (raw scores, s>t only)
__device__ float g_inv[TS];                     // 256 KB

// ---------------------------------------------------------------------------
// helpers
// ---------------------------------------------------------------------------
__device__ __forceinline__ uint32_t smem_u32(const void* p) {
    uint32_t a;
    asm("{ .reg .u64 t; cvta.to.shared.u64 t, %1; cvt.u32.u64 %0, t; }" : "=r"(a) : "l"(p));
    return a;
}
__device__ __forceinline__ void ldsm4(uint32_t* r, uint32_t a) {
    asm volatile("ldmatrix.sync.aligned.m8n8.x4.shared.b16 {%0,%1,%2,%3}, [%4];"
                 : "=r"(r[0]), "=r"(r[1]), "=r"(r[2]), "=r"(r[3]) : "r"(a));
}
__device__ __forceinline__ void mma16816(float* c, const uint32_t* a, const uint32_t* b) {
    asm volatile(
        "mma.sync.aligned.m16n8k16.row.col.f32.bf16.bf16.f32 "
        "{%0,%1,%2,%3}, {%4,%5,%6,%7}, {%8,%9}, {%0,%1,%2,%3};"
        : "+f"(c[0]), "+f"(c[1]), "+f"(c[2]), "+f"(c[3])
        : "r"(a[0]), "r"(a[1]), "r"(a[2]), "r"(a[3]), "r"(b[0]), "r"(b[1]));
}
#define CP16(sa, gp) \
    asm volatile("cp.async.ca.shared.global [%0], [%1], 16;" :: "r"(sa), "l"(gp))
#define CP_COMMIT() asm volatile("cp.async.commit_group;" ::: "memory")
#define CP_WAIT(n)  asm volatile("cp.async.wait_group %0;" :: "n"(n) : "memory")

__device__ __forceinline__ void split_bf16(float a, __nv_bfloat16& h, __nv_bfloat16& l) {
    h = __float2bfloat16_rn(a);
    l = __float2bfloat16_rn(a - __bfloat162float(h));
}

// ---------------------------------------------------------------------------
// Kernel 1: (x + pos) -> split into bf16 hi/lo
// ---------------------------------------------------------------------------
__global__ void add_split_kernel(const float* __restrict__ x,
                                 const float* __restrict__ pos,
                                 __nv_bfloat16* __restrict__ ahi,
                                 __nv_bfloat16* __restrict__ alo) {
    int i4 = blockIdx.x * blockDim.x + threadIdx.x;
    int n4 = BT * DD / 4;
    if (i4 >= n4) return;
    int td4 = i4 % (TT * DD / 4);
    float4 xv = ((const float4*)x)[i4];
    float4 pv = ((const float4*)pos)[td4];
    float a[4] = {xv.x + pv.x, xv.y + pv.y, xv.z + pv.z, xv.w + pv.w};
    __nv_bfloat16 hi[4], lo[4];
#pragma unroll
    for (int j = 0; j < 4; j++) split_bf16(a[j], hi[j], lo[j]);
    __nv_bfloat162 h0; h0.x = hi[0]; h0.y = hi[1];
    __nv_bfloat162 h1; h1.x = hi[2]; h1.y = hi[3];
    __nv_bfloat162 l0; l0.x = lo[0]; l0.y = lo[1];
    __nv_bfloat162 l1; l1.x = lo[2]; l1.y = lo[3];
    ((__nv_bfloat162*)ahi)[i4 * 2 + 0] = h0;
    ((__nv_bfloat162*)ahi)[i4 * 2 + 1] = h1;
    ((__nv_bfloat162*)alo)[i4 * 2 + 0] = l0;
    ((__nv_bfloat162*)alo)[i4 * 2 + 1] = l1;
}

// ---------------------------------------------------------------------------
// Kernel 2: weight transpose + split:  Wt_hi/lo[n][k] = split(W[k][n])
// ---------------------------------------------------------------------------
__global__ void wsplit_kernel(const float* __restrict__ W,
                              __nv_bfloat16* __restrict__ thi,
                              __nv_bfloat16* __restrict__ tlo) {
    __shared__ float tile[32][33];
    int k0 = blockIdx.x * 32;
    int n0 = blockIdx.y * 32;
    int tx = threadIdx.x;
    int ty = threadIdx.y;
#pragma unroll
    for (int i = 0; i < 32; i += 8)
        tile[ty + i][tx] = W[(size_t)(k0 + ty + i) * DD + n0 + tx];
    __syncthreads();
#pragma unroll
    for (int i = 0; i < 32; i += 8) {
        float v = tile[tx][ty + i];
        __nv_bfloat16 hi, lo;
        split_bf16(v, hi, lo);
        thi[(size_t)(n0 + ty + i) * DD + k0 + tx] = hi;
        tlo[(size_t)(n0 + ty + i) * DD + k0 + tx] = lo;
    }
}

// ---------------------------------------------------------------------------
// Kernel 3: merged HMMA projection GEMM.  grid.z = 0/1/2 -> Wq/Wk/Wv.
// z<2: epilogue writes bf16 hi/lo split (q,k).  z==2: fp32 (v).
// ---------------------------------------------------------------------------
#define G_BM 128
#define G_BN 128
#define G_BK 32
#define G_NCH (DD / G_BK)        // 32
#define G_RS 40                   // smem row stride (halfs) -> 80 B
#define G_TILE_B (128 * G_RS * 2)
#define OFF_AHI 0
#define OFF_ALO (1 * G_TILE_B)
#define OFF_BHI (2 * G_TILE_B)
#define OFF_BLO (3 * G_TILE_B)
#define G_STAGE (4 * G_TILE_B)    // 40960
#define GEMM_SMEM (2 * G_STAGE)   // 81920

__global__ __launch_bounds__(512) void gemm_hmma_kernel(
    const __nv_bfloat16* __restrict__ Ahi, const __nv_bfloat16* __restrict__ Alo,
    const __nv_bfloat16* __restrict__ Wthi, const __nv_bfloat16* __restrict__ Wtlo,
    __nv_bfloat16* __restrict__ Qhi, __nv_bfloat16* __restrict__ Qlo,
    __nv_bfloat16* __restrict__ Khi, __nv_bfloat16* __restrict__ Klo,
    float* __restrict__ V)
{
    extern __shared__ char smem[];
    const uint32_t sb = smem_u32(smem);
    const int tid = threadIdx.x;
    const int lane = tid & 31;
    const int wid = tid >> 5;
    const int wm = wid & 3;
    const int wn = wid >> 2;
    const int brow = blockIdx.y * G_BM;
    const int bcol = blockIdx.x * G_BN;
    const int z = blockIdx.z;

    const __nv_bfloat16* Bhi = Wthi + (size_t)z * DD * DD;
    const __nv_bfloat16* Blo = Wtlo + (size_t)z * DD * DD;

    const int crow = tid >> 2;
    const int cseg = tid & 3;
    const uint32_t s_off = (uint32_t)(crow * (G_RS * 2) + cseg * 16);
    const size_t ga_base = (size_t)(brow + crow) * DD + cseg * 8;
    const size_t gb_base = (size_t)(bcol + crow) * DD + cseg * 8;

    const int a_row = lane & 15;
    const int a_k8  = (lane >> 4) * 8;
    const int b_row = (lane & 7) + ((lane & 16) ? 8 : 0);
    const int b_k8  = (lane & 8) ? 8 : 0;

    float acc[2][4][4];
#pragma unroll
    for (int mt = 0; mt < 2; mt++)
#pragma unroll
        for (int nt = 0; nt < 4; nt++)
#pragma unroll
            for (int i = 0; i < 4; i++) acc[mt][nt][i] = 0.0f;

    {
        uint32_t st = sb + s_off;
        CP16(st + OFF_AHI, Ahi + ga_base);
        CP16(st + OFF_ALO, Alo + ga_base);
        CP16(st + OFF_BHI, Bhi + gb_base);
        CP16(st + OFF_BLO, Blo + gb_base);
        CP_COMMIT();
    }

    for (int ch = 0; ch < G_NCH; ch++) {
        if (ch + 1 < G_NCH) {
            uint32_t st = sb + ((ch + 1) & 1) * G_STAGE + s_off;
            size_t goff = (size_t)(ch + 1) * G_BK;
            CP16(st + OFF_AHI, Ahi + ga_base + goff);
            CP16(st + OFF_ALO, Alo + ga_base + goff);
            CP16(st + OFF_BHI, Bhi + gb_base + goff);
            CP16(st + OFF_BLO, Blo + gb_base + goff);
            CP_COMMIT();
            CP_WAIT(1);
        } else {
            CP_WAIT(0);
        }
        __syncthreads();

        const uint32_t st = sb + (ch & 1) * G_STAGE;
#pragma unroll
        for (int ks = 0; ks < 2; ks++) {
            uint32_t aH[2][4], aL[2][4];
#pragma unroll
            for (int mt = 0; mt < 2; mt++) {
                uint32_t ao = st + (uint32_t)((wm * 32 + mt * 16 + a_row) * (G_RS * 2) +
                                              (ks * 16 + a_k8) * 2);
                ldsm4(aH[mt], ao + OFF_AHI);
                ldsm4(aL[mt], ao + OFF_ALO);
            }
            uint32_t bH[2][4], bL[2][4];
#pragma unroll
            for (int p = 0; p < 2; p++) {
                uint32_t bo = st + (uint32_t)((wn * 32 + p * 16 + b_row) * (G_RS * 2) +
                                              (ks * 16 + b_k8) * 2);
                ldsm4(bH[p], bo + OFF_BHI);
                ldsm4(bL[p], bo + OFF_BLO);
            }
#pragma unroll
            for (int mt = 0; mt < 2; mt++)
#pragma unroll
                for (int nt = 0; nt < 4; nt++) {
                    const uint32_t* bh = &bH[nt >> 1][(nt & 1) * 2];
                    const uint32_t* bl = &bL[nt >> 1][(nt & 1) * 2];
                    mma16816(acc[mt][nt], aH[mt], bh);
                    mma16816(acc[mt][nt], aH[mt], bl);
                    mma16816(acc[mt][nt], aL[mt], bh);
                }
        }
        __syncthreads();
    }

    __nv_bfloat16* Ohi = (z == 0) ? Qhi : Khi;
    __nv_bfloat16* Olo = (z == 0) ? Qlo : Klo;
#pragma unroll
    for (int mt = 0; mt < 2; mt++) {
        int row = brow + wm * 32 + mt * 16 + (lane >> 2);
#pragma unroll
        for (int nt = 0; nt < 4; nt++) {
            int col = bcol + wn * 32 + nt * 8 + (lane & 3) * 2;
            if (z == 2) {
                *(float2*)(V + (size_t)row * DD + col) =
                    make_float2(acc[mt][nt][0], acc[mt][nt][1]);
                *(float2*)(V + (size_t)(row + 8) * DD + col) =
                    make_float2(acc[mt][nt][2], acc[mt][nt][3]);
            } else {
#pragma unroll
                for (int half = 0; half < 2; half++) {
                    int r = row + half * 8;
                    __nv_bfloat16 h0, l0, h1, l1;
                    split_bf16(acc[mt][nt][half * 2 + 0], h0, l0);
                    split_bf16(acc[mt][nt][half * 2 + 1], h1, l1);
                    __nv_bfloat162 hp; hp.x = h0; hp.y = h1;
                    __nv_bfloat162 lp; lp.x = l0; lp.y = l1;
                    *(__nv_bfloat162*)(Ohi + (size_t)r * DD + col) = hp;
                    *(__nv_bfloat162*)(Olo + (size_t)r * DD + col) = lp;
                }
            }
        }
    }
}

// ---------------------------------------------------------------------------
// Kernel 4: HMMA scores.  scores[bh][t][s] = (q.k)/16 for s>t, raw.
// One 64x64 tile per CTA, no k-loop (dh=64). 8 warps: wm in 0..3 (m16),
// wn in 0..1 (n32). 3-product split-bf16.
// ---------------------------------------------------------------------------
#define SC_STR 72   // smem row stride in halfs (144B -> conflict-free ldmatrix)

__global__ __launch_bounds__(256) void scores_hmma_kernel(
    const __nv_bfloat16* __restrict__ qhi, const __nv_bfloat16* __restrict__ qlo,
    const __nv_bfloat16* __restrict__ khi, const __nv_bfloat16* __restrict__ klo,
    float* __restrict__ scores)
{
    const int t0 = blockIdx.y * 64;
    const int s0 = blockIdx.x * 64;
    if (s0 < t0) return;   // fully masked tile
    const int bh = blockIdx.z;
    const int b = bh & (BB - 1);
    const int h = bh >> 6;

    __shared__ __nv_bfloat16 sm[4][64 * SC_STR];

    const int tid = threadIdx.x;
    const int lane = tid & 31;
    const int wid = tid >> 5;
    const int wm = wid & 3;
    const int wn = wid >> 2;

    const __nv_bfloat16* gsrc[4] = {qhi, qlo, khi, klo};
#pragma unroll
    for (int tz = 0; tz < 4; tz++) {
        const __nv_bfloat16* g = gsrc[tz];
        const int rowbase = (tz < 2) ? t0 : s0;
        uint32_t sbase = smem_u32(&sm[tz][0]);
#pragma unroll
        for (int i = 0; i < 2; i++) {
            int idx = tid + i * 256;       // 0..511
            int r = idx >> 3;              // 0..63
            int seg = idx & 7;             // 16B segment
            uint32_t sa = sbase + (uint32_t)(r * SC_STR * 2 + seg * 16);
            const __nv_bfloat16* gp = g + (size_t)(b * TT + rowbase + r) * DD +
                                      h * DH + seg * 8;
            CP16(sa, gp);
        }
    }
    CP_COMMIT(); CP_WAIT(0);
    __syncthreads();

    const uint32_t qh_b = smem_u32(&sm[0][0]);
    const uint32_t ql_b = smem_u32(&sm[1][0]);
    const uint32_t kh_b = smem_u32(&sm[2][0]);
    const uint32_t kl_b = smem_u32(&sm[3][0]);

    const int a_row = lane & 15;
    const int a_k8  = (lane >> 4) * 8;
    const int b_row = (lane & 7) + ((lane & 16) ? 8 : 0);
    const int b_k8  = (lane & 8) ? 8 : 0;

    float acc[4][4];
#pragma unroll
    for (int nt = 0; nt < 4; nt++)
#pragma unroll
        for (int i = 0; i < 4; i++) acc[nt][i] = 0.0f;

#pragma unroll
    for (int ks = 0; ks < 4; ks++) {
        uint32_t aH[4], aL[4];
        uint32_t ao = (uint32_t)((wm * 16 + a_row) * SC_STR * 2 + (ks * 16 + a_k8) * 2);
        ldsm4(aH, qh_b + ao);
        ldsm4(aL, ql_b + ao);
        uint32_t bH[2][4], bL[2][4];
#pragma unroll
        for (int p = 0; p < 2; p++) {
            uint32_t bo = (uint32_t)((wn * 32 + p * 16 + b_row) * SC_STR * 2 +
                                     (ks * 16 + b_k8) * 2);
            ldsm4(bH[p], kh_b + bo);
            ldsm4(bL[p], kl_b + bo);
        }
#pragma unroll
        for (int nt = 0; nt < 4; nt++) {
            const uint32_t* bhp = &bH[nt >> 1][(nt & 1) * 2];
            const uint32_t* blp = &bL[nt >> 1][(nt & 1) * 2];
            mma16816(acc[nt], aH, bhp);
            mma16816(acc[nt], aH, blp);
            mma16816(acc[nt], aL, bhp);
        }
    }

    float* outp = scores + (size_t)bh * TS;
    const int row0 = t0 + wm * 16 + (lane >> 2);
#pragma unroll
    for (int nt = 0; nt < 4; nt++) {
        int col = s0 + wn * 32 + nt * 8 + (lane & 3) * 2;
#pragma unroll
        for (int half = 0; half < 2; half++) {
            int r = row0 + half * 8;
            float c0 = acc[nt][half * 2 + 0] * 0.0625f;
            float c1 = acc[nt][half * 2 + 1] * 0.0625f;
            if (col > r)     outp[r * TT + col]     = c0;
            if (col + 1 > r) outp[r * TT + col + 1] = c1;
        }
    }
}

// ---------------------------------------------------------------------------
// Kernel 5: expsum over bh -> inv (unmasked columns only)
// ---------------------------------------------------------------------------
__global__ void expsum_kernel(const float* __restrict__ scores,
                              float* __restrict__ inv) {
    int ts = blockIdx.x * blockDim.x + threadIdx.x;
    if (ts >= TS) return;
    int t = ts >> 8;
    int s = ts & 255;
    if (s <= t) return;
    const float* p = scores + ts;
    float sum = 0.0f;
#pragma unroll 8
    for (int bh = 0; bh < HB; bh++) sum += __expf(p[bh * TS]);
    inv[ts] = 1.0f / sum;
}

// ---------------------------------------------------------------------------
// Kernel 6: out = probs @ v_ ; masked region via uniform * V column-sum
// ---------------------------------------------------------------------------
__global__ __launch_bounds__(256) void out_kernel(const float* __restrict__ scores,
                                                  const float* __restrict__ inv,
                                                  const float* __restrict__ v,
                                                  float* __restrict__ out) {
    const int bh = blockIdx.y;
    const int b = bh & (BB - 1);
    const int h = bh >> 6;
    const int t0 = blockIdx.x * 64;

    __shared__ float Ps[64][65];
    __shared__ float Vs[64][65];

    const int tid = threadIdx.x;
    const float* sbase = scores + (size_t)bh * TS;
    const float* vbase = v + (size_t)b * TT * DD + h * DH;

    const int trow = (tid / 16) * 4;
    const int tcol = (tid % 16) * 4;
    float acc[4][4];
    float cs[4] = {0.0f, 0.0f, 0.0f, 0.0f};
#pragma unroll
    for (int i = 0; i < 4; i++)
#pragma unroll
        for (int j = 0; j < 4; j++) acc[i][j] = 0.0f;

    for (int s0 = 0; s0 < TT; s0 += 64) {
        const bool full_masked = (s0 + 64 <= t0);
#pragma unroll
        for (int i = 0; i < 4; i++) {
            int idx = tid + i * 256;
            int r = idx >> 4;
            int c = (idx & 15) * 4;
            float4 vv = *(const float4*)(vbase + (size_t)(s0 + r) * DD + c);
            Vs[r][c] = vv.x; Vs[r][c + 1] = vv.y; Vs[r][c + 2] = vv.z; Vs[r][c + 3] = vv.w;
        }
        if (!full_masked) {
#pragma unroll
            for (int i = 0; i < 4; i++) {
                int idx = tid + i * 256;
                int r = idx >> 4;
                int c4 = (idx & 15) * 4;
#pragma unroll
                for (int j = 0; j < 4; j++) {
                    int t = t0 + r;
                    int s = s0 + c4 + j;
                    float w;
                    if (s <= t) w = UNIF;
                    else        w = __expf(sbase[t * TT + s]) * inv[t * TT + s];
                    Ps[r][c4 + j] = w;
                }
            }
        }
        __syncthreads();

        if (full_masked) {
#pragma unroll 8
            for (int kk = 0; kk < 64; kk++) {
#pragma unroll
                for (int j = 0; j < 4; j++) cs[j] += Vs[kk][tcol + j];
            }
        } else {
#pragma unroll 8
            for (int kk = 0; kk < 64; kk++) {
                float rp[4], rv[4];
#pragma unroll
                for (int i = 0; i < 4; i++) rp[i] = Ps[trow + i][kk];
#pragma unroll
                for (int j = 0; j < 4; j++) rv[j] = Vs[kk][tcol + j];
#pragma unroll
                for (int i = 0; i < 4; i++)
#pragma unroll
                    for (int j = 0; j < 4; j++) acc[i][j] = fmaf(rp[i], rv[j], acc[i][j]);
            }
        }
        __syncthreads();
    }

    float* obase = out + (size_t)(b * TT + t0) * DD + h * DH;
#pragma unroll
    for (int i = 0; i < 4; i++) {
        float* op = obase + (size_t)(trow + i) * DD + tcol;
        *(float4*)op = make_float4(acc[i][0] + UNIF * cs[0],
                                   acc[i][1] + UNIF * cs[1],
                                   acc[i][2] + UNIF * cs[2],
                                   acc[i][3] + UNIF * cs[3]);
    }
}

// ---------------------------------------------------------------------------
// Launch
// ---------------------------------------------------------------------------
extern "C" void kernel_launch(void* const* d_in, const int* in_sizes, int n_in,
                              void* d_out, int out_size) {
    const float* x   = (const float*)d_in[0];
    const float* pos = (const float*)d_in[1];
    const float* W[3] = {(const float*)d_in[2], (const float*)d_in[3], (const float*)d_in[4]};
    float* out = (float*)d_out;

    __nv_bfloat16 *ahi, *alo, *wthi, *wtlo, *qhi, *qlo, *khi, *klo;
    float *v, *scores, *inv;
    cudaGetSymbolAddress((void**)&ahi, g_ahi);
    cudaGetSymbolAddress((void**)&alo, g_alo);
    cudaGetSymbolAddress((void**)&wthi, g_wthi);
    cudaGetSymbolAddress((void**)&wtlo, g_wtlo);
    cudaGetSymbolAddress((void**)&qhi, g_qhi);
    cudaGetSymbolAddress((void**)&qlo, g_qlo);
    cudaGetSymbolAddress((void**)&khi, g_khi);
    cudaGetSymbolAddress((void**)&klo, g_klo);
    cudaGetSymbolAddress((void**)&v, g_v);
    cudaGetSymbolAddress((void**)&scores, g_scores);
    cudaGetSymbolAddress((void**)&inv, g_inv);

    cudaFuncSetAttribute(gemm_hmma_kernel,
                         cudaFuncAttributeMaxDynamicSharedMemorySize, GEMM_SMEM);

    // 1. (x + pos) -> bf16 hi/lo split
    {
        int n4 = BT * DD / 4;
        add_split_kernel<<<(n4 + 255) / 256, 256>>>(x, pos, ahi, alo);
    }

    // 2. weight transpose + split (x3)
    {
        dim3 blk(32, 8);
        dim3 grid(DD / 32, DD / 32);
        for (int i = 0; i < 3; i++)
            wsplit_kernel<<<grid, blk>>>(W[i], wthi + (size_t)i * DD * DD,
                                         wtlo + (size_t)i * DD * DD);
    }

    // 3. merged q/k/v projections (q,k -> bf16 split epilogue; v -> fp32)
    {
        dim3 grid(DD / G_BN, BT / G_BM, 3);
        gemm_hmma_kernel<<<grid, 512, GEMM_SMEM>>>(
            ahi, alo, wthi, wtlo, qhi, qlo, khi, klo, v);
    }

    // 4. raw masked scores via HMMA (upper-triangular tiles only)
    {
        dim3 grid(TT / 64, TT / 64, HB);
        scores_hmma_kernel<<<grid, 256>>>(qhi, qlo, khi, klo, scores);
    }

    // 5. per-(t,s) exp-sum over bh -> inv
    expsum_kernel<<<TS / 256, 256>>>(scores, inv);

    // 6. output
    {
        dim3 grid(TT / 64, HB);
        out_kernel<<<grid, 256>>>(scores, inv, v, out);
    }
}

// round 6
// speedup vs baseline: 2.4501x; 1.0285x over previous
#include <cuda_runtime.h>
#include <cuda_bf16.h>
#include <math.h>
#include <stdint.h>

// Problem constants
#define BB   64
#define TT   256
#define DD   1024
#define HH   16
#define DH   64
#define BT   (BB*TT)      // 16384
#define HB   (HH*BB)      // 1024
#define TS   (TT*TT)      // 65536

#define UNIF (1.0f / 1024.0f)   // exactly representable in bf16

// ---------------------------------------------------------------------------
// Scratch (__device__ globals; no allocation allowed)
// ---------------------------------------------------------------------------
__device__ __nv_bfloat16 g_ahi[BT * DD];        // 32 MB
__device__ __nv_bfloat16 g_alo[BT * DD];        // 32 MB
__device__ __nv_bfloat16 g_wthi[3][DD * DD];    // 2 MB x3  (transposed: [n][k])
__device__ __nv_bfloat16 g_wtlo[3][DD * DD];    // 2 MB x3
__device__ __nv_bfloat16 g_qhi[BT * DD];        // 32 MB
__device__ __nv_bfloat16 g_qlo[BT * DD];        // 32 MB
__device__ __nv_bfloat16 g_khi[BT * DD];        // 32 MB
__device__ __nv_bfloat16 g_klo[BT * DD];        // 32 MB
__device__ float g_v[BT * DD];                  // 64 MB
__device__ float g_scores[(size_t)HB * TS];     // 256 MB (raw scores, s>t valid)
__device__ float g_inv[TS];                     // 256 KB

// ---------------------------------------------------------------------------
// helpers
// ---------------------------------------------------------------------------
__device__ __forceinline__ uint32_t smem_u32(const void* p) {
    uint32_t a;
    asm("{ .reg .u64 t; cvta.to.shared.u64 t, %1; cvt.u32.u64 %0, t; }" : "=r"(a) : "l"(p));
    return a;
}
__device__ __forceinline__ void ldsm4(uint32_t* r, uint32_t a) {
    asm volatile("ldmatrix.sync.aligned.m8n8.x4.shared.b16 {%0,%1,%2,%3}, [%4];"
                 : "=r"(r[0]), "=r"(r[1]), "=r"(r[2]), "=r"(r[3]) : "r"(a));
}
__device__ __forceinline__ void mma16816(float* c, const uint32_t* a, const uint32_t* b) {
    asm volatile(
        "mma.sync.aligned.m16n8k16.row.col.f32.bf16.bf16.f32 "
        "{%0,%1,%2,%3}, {%4,%5,%6,%7}, {%8,%9}, {%0,%1,%2,%3};"
        : "+f"(c[0]), "+f"(c[1]), "+f"(c[2]), "+f"(c[3])
        : "r"(a[0]), "r"(a[1]), "r"(a[2]), "r"(a[3]), "r"(b[0]), "r"(b[1]));
}
#define CP16(sa, gp) \
    asm volatile("cp.async.cg.shared.global [%0], [%1], 16;" :: "r"(sa), "l"(gp))
#define CP_COMMIT() asm volatile("cp.async.commit_group;" ::: "memory")
#define CP_WAIT(n)  asm volatile("cp.async.wait_group %0;" :: "n"(n) : "memory")

__device__ __forceinline__ void split_bf16(float a, __nv_bfloat16& h, __nv_bfloat16& l) {
    h = __float2bfloat16_rn(a);
    l = __float2bfloat16_rn(a - __bfloat162float(h));
}

// ---------------------------------------------------------------------------
// Kernel 1: (x + pos) -> split into bf16 hi/lo
// ---------------------------------------------------------------------------
__global__ void add_split_kernel(const float* __restrict__ x,
                                 const float* __restrict__ pos,
                                 __nv_bfloat16* __restrict__ ahi,
                                 __nv_bfloat16* __restrict__ alo) {
    int i4 = blockIdx.x * blockDim.x + threadIdx.x;
    int n4 = BT * DD / 4;
    if (i4 >= n4) return;
    int td4 = i4 % (TT * DD / 4);
    float4 xv = ((const float4*)x)[i4];
    float4 pv = ((const float4*)pos)[td4];
    float a[4] = {xv.x + pv.x, xv.y + pv.y, xv.z + pv.z, xv.w + pv.w};
    __nv_bfloat16 hi[4], lo[4];
#pragma unroll
    for (int j = 0; j < 4; j++) split_bf16(a[j], hi[j], lo[j]);
    __nv_bfloat162 h0; h0.x = hi[0]; h0.y = hi[1];
    __nv_bfloat162 h1; h1.x = hi[2]; h1.y = hi[3];
    __nv_bfloat162 l0; l0.x = lo[0]; l0.y = lo[1];
    __nv_bfloat162 l1; l1.x = lo[2]; l1.y = lo[3];
    ((__nv_bfloat162*)ahi)[i4 * 2 + 0] = h0;
    ((__nv_bfloat162*)ahi)[i4 * 2 + 1] = h1;
    ((__nv_bfloat162*)alo)[i4 * 2 + 0] = l0;
    ((__nv_bfloat162*)alo)[i4 * 2 + 1] = l1;
}

// ---------------------------------------------------------------------------
// Kernel 2: weight transpose + split:  Wt_hi/lo[n][k] = split(W[k][n])
// ---------------------------------------------------------------------------
__global__ void wsplit_kernel(const float* __restrict__ W,
                              __nv_bfloat16* __restrict__ thi,
                              __nv_bfloat16* __restrict__ tlo) {
    __shared__ float tile[32][33];
    int k0 = blockIdx.x * 32;
    int n0 = blockIdx.y * 32;
    int tx = threadIdx.x;
    int ty = threadIdx.y;
#pragma unroll
    for (int i = 0; i < 32; i += 8)
        tile[ty + i][tx] = W[(size_t)(k0 + ty + i) * DD + n0 + tx];
    __syncthreads();
#pragma unroll
    for (int i = 0; i < 32; i += 8) {
        float v = tile[tx][ty + i];
        __nv_bfloat16 hi, lo;
        split_bf16(v, hi, lo);
        thi[(size_t)(n0 + ty + i) * DD + k0 + tx] = hi;
        tlo[(size_t)(n0 + ty + i) * DD + k0 + tx] = lo;
    }
}

// ---------------------------------------------------------------------------
// Kernel 3: merged HMMA projection GEMM. grid = (24, 128):
// x = (z<<3)|n-tile, so 24 launch-adjacent CTAs share one A row-block (L2).
// z<2: epilogue writes bf16 hi/lo split (q,k).  z==2: fp32 (v).
// ---------------------------------------------------------------------------
#define G_BM 128
#define G_BN 128
#define G_BK 32
#define G_NCH (DD / G_BK)        // 32
#define G_RS 40                   // smem row stride (halfs) -> 80 B
#define G_TILE_B (128 * G_RS * 2)
#define OFF_AHI 0
#define OFF_ALO (1 * G_TILE_B)
#define OFF_BHI (2 * G_TILE_B)
#define OFF_BLO (3 * G_TILE_B)
#define G_STAGE (4 * G_TILE_B)    // 40960
#define GEMM_SMEM (2 * G_STAGE)   // 81920

__global__ __launch_bounds__(512) void gemm_hmma_kernel(
    const __nv_bfloat16* __restrict__ Ahi, const __nv_bfloat16* __restrict__ Alo,
    const __nv_bfloat16* __restrict__ Wthi, const __nv_bfloat16* __restrict__ Wtlo,
    __nv_bfloat16* __restrict__ Qhi, __nv_bfloat16* __restrict__ Qlo,
    __nv_bfloat16* __restrict__ Khi, __nv_bfloat16* __restrict__ Klo,
    float* __restrict__ V)
{
    extern __shared__ char smem[];
    const uint32_t sb = smem_u32(smem);
    const int tid = threadIdx.x;
    const int lane = tid & 31;
    const int wid = tid >> 5;
    const int wm = wid & 3;
    const int wn = wid >> 2;
    const int z = blockIdx.x >> 3;
    const int brow = blockIdx.y * G_BM;
    const int bcol = (blockIdx.x & 7) * G_BN;

    const __nv_bfloat16* Bhi = Wthi + (size_t)z * DD * DD;
    const __nv_bfloat16* Blo = Wtlo + (size_t)z * DD * DD;

    const int crow = tid >> 2;
    const int cseg = tid & 3;
    const uint32_t s_off = (uint32_t)(crow * (G_RS * 2) + cseg * 16);
    const size_t ga_base = (size_t)(brow + crow) * DD + cseg * 8;
    const size_t gb_base = (size_t)(bcol + crow) * DD + cseg * 8;

    const int a_row = lane & 15;
    const int a_k8  = (lane >> 4) * 8;
    const int b_row = (lane & 7) + ((lane & 16) ? 8 : 0);
    const int b_k8  = (lane & 8) ? 8 : 0;

    float acc[2][4][4];
#pragma unroll
    for (int mt = 0; mt < 2; mt++)
#pragma unroll
        for (int nt = 0; nt < 4; nt++)
#pragma unroll
            for (int i = 0; i < 4; i++) acc[mt][nt][i] = 0.0f;

    {
        uint32_t st = sb + s_off;
        CP16(st + OFF_AHI, Ahi + ga_base);
        CP16(st + OFF_ALO, Alo + ga_base);
        CP16(st + OFF_BHI, Bhi + gb_base);
        CP16(st + OFF_BLO, Blo + gb_base);
        CP_COMMIT();
    }

    for (int ch = 0; ch < G_NCH; ch++) {
        if (ch + 1 < G_NCH) {
            uint32_t st = sb + ((ch + 1) & 1) * G_STAGE + s_off;
            size_t goff = (size_t)(ch + 1) * G_BK;
            CP16(st + OFF_AHI, Ahi + ga_base + goff);
            CP16(st + OFF_ALO, Alo + ga_base + goff);
            CP16(st + OFF_BHI, Bhi + gb_base + goff);
            CP16(st + OFF_BLO, Blo + gb_base + goff);
            CP_COMMIT();
            CP_WAIT(1);
        } else {
            CP_WAIT(0);
        }
        __syncthreads();

        const uint32_t st = sb + (ch & 1) * G_STAGE;
#pragma unroll
        for (int ks = 0; ks < 2; ks++) {
            uint32_t aH[2][4], aL[2][4];
#pragma unroll
            for (int mt = 0; mt < 2; mt++) {
                uint32_t ao = st + (uint32_t)((wm * 32 + mt * 16 + a_row) * (G_RS * 2) +
                                              (ks * 16 + a_k8) * 2);
                ldsm4(aH[mt], ao + OFF_AHI);
                ldsm4(aL[mt], ao + OFF_ALO);
            }
            uint32_t bH[2][4], bL[2][4];
#pragma unroll
            for (int p = 0; p < 2; p++) {
                uint32_t bo = st + (uint32_t)((wn * 32 + p * 16 + b_row) * (G_RS * 2) +
                                              (ks * 16 + b_k8) * 2);
                ldsm4(bH[p], bo + OFF_BHI);
                ldsm4(bL[p], bo + OFF_BLO);
            }
#pragma unroll
            for (int mt = 0; mt < 2; mt++)
#pragma unroll
                for (int nt = 0; nt < 4; nt++) {
                    const uint32_t* bh = &bH[nt >> 1][(nt & 1) * 2];
                    const uint32_t* bl = &bL[nt >> 1][(nt & 1) * 2];
                    mma16816(acc[mt][nt], aH[mt], bh);
                    mma16816(acc[mt][nt], aH[mt], bl);
                    mma16816(acc[mt][nt], aL[mt], bh);
                }
        }
        __syncthreads();
    }

    __nv_bfloat16* Ohi = (z == 0) ? Qhi : Khi;
    __nv_bfloat16* Olo = (z == 0) ? Qlo : Klo;
#pragma unroll
    for (int mt = 0; mt < 2; mt++) {
        int row = brow + wm * 32 + mt * 16 + (lane >> 2);
#pragma unroll
        for (int nt = 0; nt < 4; nt++) {
            int col = bcol + wn * 32 + nt * 8 + (lane & 3) * 2;
            if (z == 2) {
                *(float2*)(V + (size_t)row * DD + col) =
                    make_float2(acc[mt][nt][0], acc[mt][nt][1]);
                *(float2*)(V + (size_t)(row + 8) * DD + col) =
                    make_float2(acc[mt][nt][2], acc[mt][nt][3]);
            } else {
#pragma unroll
                for (int half = 0; half < 2; half++) {
                    int r = row + half * 8;
                    __nv_bfloat16 h0, l0, h1, l1;
                    split_bf16(acc[mt][nt][half * 2 + 0], h0, l0);
                    split_bf16(acc[mt][nt][half * 2 + 1], h1, l1);
                    __nv_bfloat162 hp; hp.x = h0; hp.y = h1;
                    __nv_bfloat162 lp; lp.x = l0; lp.y = l1;
                    *(__nv_bfloat162*)(Ohi + (size_t)r * DD + col) = hp;
                    *(__nv_bfloat162*)(Olo + (size_t)r * DD + col) = lp;
                }
            }
        }
    }
}

// ---------------------------------------------------------------------------
// Kernel 4: HMMA scores. Unconditional vector stores (masked slots are
// garbage and provably never read).
// ---------------------------------------------------------------------------
#define SC_STR 72   // smem row stride in halfs (144B)

__global__ __launch_bounds__(256) void scores_hmma_kernel(
    const __nv_bfloat16* __restrict__ qhi, const __nv_bfloat16* __restrict__ qlo,
    const __nv_bfloat16* __restrict__ khi, const __nv_bfloat16* __restrict__ klo,
    float* __restrict__ scores)
{
    const int t0 = blockIdx.y * 64;
    const int s0 = blockIdx.x * 64;
    if (s0 < t0) return;   // fully masked tile
    const int bh = blockIdx.z;
    const int b = bh & (BB - 1);
    const int h = bh >> 6;

    __shared__ __nv_bfloat16 sm[4][64 * SC_STR];

    const int tid = threadIdx.x;
    const int lane = tid & 31;
    const int wid = tid >> 5;
    const int wm = wid & 3;
    const int wn = wid >> 2;

    const __nv_bfloat16* gsrc[4] = {qhi, qlo, khi, klo};
#pragma unroll
    for (int tz = 0; tz < 4; tz++) {
        const __nv_bfloat16* g = gsrc[tz];
        const int rowbase = (tz < 2) ? t0 : s0;
        uint32_t sbase = smem_u32(&sm[tz][0]);
#pragma unroll
        for (int i = 0; i < 2; i++) {
            int idx = tid + i * 256;
            int r = idx >> 3;
            int seg = idx & 7;
            uint32_t sa = sbase + (uint32_t)(r * SC_STR * 2 + seg * 16);
            const __nv_bfloat16* gp = g + (size_t)(b * TT + rowbase + r) * DD +
                                      h * DH + seg * 8;
            CP16(sa, gp);
        }
    }
    CP_COMMIT(); CP_WAIT(0);
    __syncthreads();

    const uint32_t qh_b = smem_u32(&sm[0][0]);
    const uint32_t ql_b = smem_u32(&sm[1][0]);
    const uint32_t kh_b = smem_u32(&sm[2][0]);
    const uint32_t kl_b = smem_u32(&sm[3][0]);

    const int a_row = lane & 15;
    const int a_k8  = (lane >> 4) * 8;
    const int b_row = (lane & 7) + ((lane & 16) ? 8 : 0);
    const int b_k8  = (lane & 8) ? 8 : 0;

    float acc[4][4];
#pragma unroll
    for (int nt = 0; nt < 4; nt++)
#pragma unroll
        for (int i = 0; i < 4; i++) acc[nt][i] = 0.0f;

#pragma unroll
    for (int ks = 0; ks < 4; ks++) {
        uint32_t aH[4], aL[4];
        uint32_t ao = (uint32_t)((wm * 16 + a_row) * SC_STR * 2 + (ks * 16 + a_k8) * 2);
        ldsm4(aH, qh_b + ao);
        ldsm4(aL, ql_b + ao);
        uint32_t bH[2][4], bL[2][4];
#pragma unroll
        for (int p = 0; p < 2; p++) {
            uint32_t bo = (uint32_t)((wn * 32 + p * 16 + b_row) * SC_STR * 2 +
                                     (ks * 16 + b_k8) * 2);
            ldsm4(bH[p], kh_b + bo);
            ldsm4(bL[p], kl_b + bo);
        }
#pragma unroll
        for (int nt = 0; nt < 4; nt++) {
            const uint32_t* bhp = &bH[nt >> 1][(nt & 1) * 2];
            const uint32_t* blp = &bL[nt >> 1][(nt & 1) * 2];
            mma16816(acc[nt], aH, bhp);
            mma16816(acc[nt], aH, blp);
            mma16816(acc[nt], aL, bhp);
        }
    }

    float* outp = scores + (size_t)bh * TS;
    const int row0 = t0 + wm * 16 + (lane >> 2);
#pragma unroll
    for (int nt = 0; nt < 4; nt++) {
        int col = s0 + wn * 32 + nt * 8 + (lane & 3) * 2;
#pragma unroll
        for (int half = 0; half < 2; half++) {
            int r = row0 + half * 8;
            *(float2*)(outp + r * TT + col) =
                make_float2(acc[nt][half * 2 + 0] * 0.0625f,
                            acc[nt][half * 2 + 1] * 0.0625f);
        }
    }
}

// ---------------------------------------------------------------------------
// Kernel 5: expsum over bh -> inv (unmasked columns only)
// ---------------------------------------------------------------------------
__global__ void expsum_kernel(const float* __restrict__ scores,
                              float* __restrict__ inv) {
    int ts = blockIdx.x * blockDim.x + threadIdx.x;
    if (ts >= TS) return;
    int t = ts >> 8;
    int s = ts & 255;
    if (s <= t) return;
    const float* p = scores + ts;
    float sum = 0.0f;
#pragma unroll 8
    for (int bh = 0; bh < HB; bh++) sum += __expf(p[bh * TS]);
    inv[ts] = 1.0f / sum;
}

// ---------------------------------------------------------------------------
// Kernel 6: out = probs @ v_ on HMMA (split-bf16 probs & V).
// Ps[t][s] = UNIF (s<=t) or exp(score)*inv; V transposed to Vt[d][s].
// 3-product MMA; fully-masked tiles use Ps_hi=UNIF, Ps_lo=0 (skip lo product).
// ---------------------------------------------------------------------------
__global__ __launch_bounds__(256) void out_hmma_kernel(
    const float* __restrict__ scores,
    const float* __restrict__ inv,
    const float* __restrict__ v,
    float* __restrict__ out)
{
    const int bh = blockIdx.y;
    const int b = bh & (BB - 1);
    const int h = bh >> 6;
    const int t0 = blockIdx.x * 64;

    __shared__ __nv_bfloat16 Ph[64 * SC_STR];
    __shared__ __nv_bfloat16 Pl[64 * SC_STR];
    __shared__ __nv_bfloat16 Vh[64 * SC_STR];   // [d][s]
    __shared__ __nv_bfloat16 Vl[64 * SC_STR];

    const int tid = threadIdx.x;
    const int lane = tid & 31;
    const int wid = tid >> 5;
    const int wm = wid & 3;        // t 16-block
    const int wn = wid >> 2;       // d 32-block

    const float* sbase = scores + (size_t)bh * TS;
    const float* vbase = v + (size_t)b * TT * DD + h * DH;

    const uint32_t ph_b = smem_u32(Ph);
    const uint32_t pl_b = smem_u32(Pl);
    const uint32_t vh_b = smem_u32(Vh);
    const uint32_t vl_b = smem_u32(Vl);

    const int a_row = lane & 15;
    const int a_k8  = (lane >> 4) * 8;
    const int b_row = (lane & 7) + ((lane & 16) ? 8 : 0);
    const int b_k8  = (lane & 8) ? 8 : 0;

    float acc[4][4];
#pragma unroll
    for (int nt = 0; nt < 4; nt++)
#pragma unroll
        for (int i = 0; i < 4; i++) acc[nt][i] = 0.0f;

    for (int s0 = 0; s0 < TT; s0 += 64) {
        const bool full_masked = (s0 + 64 <= t0);

        // V tile -> transposed split  Vt[d][s]
#pragma unroll
        for (int i = 0; i < 4; i++) {
            int idx = tid + i * 256;          // 0..1023 float4 slots
            int s = idx >> 4;                 // 0..63
            int d4 = (idx & 15) * 4;          // 0..60
            float4 vv = *(const float4*)(vbase + (size_t)(s0 + s) * DD + d4);
            float vals[4] = {vv.x, vv.y, vv.z, vv.w};
#pragma unroll
            for (int j = 0; j < 4; j++) {
                __nv_bfloat16 hi, lo;
                split_bf16(vals[j], hi, lo);
                Vh[(d4 + j) * SC_STR + s] = hi;
                Vl[(d4 + j) * SC_STR + s] = lo;
            }
        }

        // Ps tile
        if (full_masked) {
            const __nv_bfloat16 uh = __float2bfloat16_rn(UNIF);
#pragma unroll
            for (int i = 0; i < 4; i++) {
                int idx = tid + i * 256;
                int r = idx >> 4;
                int c4 = (idx & 15) * 4;
#pragma unroll
                for (int j = 0; j < 4; j++)
                    Ph[r * SC_STR + c4 + j] = uh;
            }
        } else {
#pragma unroll
            for (int i = 0; i < 4; i++) {
                int idx = tid + i * 256;
                int r = idx >> 4;             // t row 0..63
                int c4 = (idx & 15) * 4;      // s col
                int t = t0 + r;
                float4 sc = *(const float4*)(sbase + t * TT + s0 + c4);
                float4 iv = *(const float4*)(inv + t * TT + s0 + c4);
                float scs[4] = {sc.x, sc.y, sc.z, sc.w};
                float ivs[4] = {iv.x, iv.y, iv.z, iv.w};
#pragma unroll
                for (int j = 0; j < 4; j++) {
                    int s = s0 + c4 + j;
                    float w = (s <= t) ? UNIF : __expf(scs[j]) * ivs[j];
                    __nv_bfloat16 hi, lo;
                    split_bf16(w, hi, lo);
                    Ph[r * SC_STR + c4 + j] = hi;
                    Pl[r * SC_STR + c4 + j] = lo;
                }
            }
        }
        __syncthreads();

#pragma unroll
        for (int ks = 0; ks < 4; ks++) {
            uint32_t aH[4], aL[4];
            uint32_t ao = (uint32_t)((wm * 16 + a_row) * SC_STR * 2 + (ks * 16 + a_k8) * 2);
            ldsm4(aH, ph_b + ao);
            if (!full_masked) ldsm4(aL, pl_b + ao);
            uint32_t bH[2][4], bL[2][4];
#pragma unroll
            for (int p = 0; p < 2; p++) {
                uint32_t bo = (uint32_t)((wn * 32 + p * 16 + b_row) * SC_STR * 2 +
                                         (ks * 16 + b_k8) * 2);
                ldsm4(bH[p], vh_b + bo);
                ldsm4(bL[p], vl_b + bo);
            }
#pragma unroll
            for (int nt = 0; nt < 4; nt++) {
                const uint32_t* bhp = &bH[nt >> 1][(nt & 1) * 2];
                const uint32_t* blp = &bL[nt >> 1][(nt & 1) * 2];
                mma16816(acc[nt], aH, bhp);
                mma16816(acc[nt], aH, blp);
                if (!full_masked) mma16816(acc[nt], aL, bhp);
            }
        }
        __syncthreads();
    }

    const int row0 = t0 + wm * 16 + (lane >> 2);
#pragma unroll
    for (int nt = 0; nt < 4; nt++) {
        int col = wn * 32 + nt * 8 + (lane & 3) * 2;
#pragma unroll
        for (int half = 0; half < 2; half++) {
            int r = row0 + half * 8;
            *(float2*)(out + (size_t)(b * TT + r) * DD + h * DH + col) =
                make_float2(acc[nt][half * 2 + 0], acc[nt][half * 2 + 1]);
        }
    }
}

// ---------------------------------------------------------------------------
// Launch
// ---------------------------------------------------------------------------
extern "C" void kernel_launch(void* const* d_in, const int* in_sizes, int n_in,
                              void* d_out, int out_size) {
    const float* x   = (const float*)d_in[0];
    const float* pos = (const float*)d_in[1];
    const float* W[3] = {(const float*)d_in[2], (const float*)d_in[3], (const float*)d_in[4]};
    float* out = (float*)d_out;

    __nv_bfloat16 *ahi, *alo, *wthi, *wtlo, *qhi, *qlo, *khi, *klo;
    float *v, *scores, *inv;
    cudaGetSymbolAddress((void**)&ahi, g_ahi);
    cudaGetSymbolAddress((void**)&alo, g_alo);
    cudaGetSymbolAddress((void**)&wthi, g_wthi);
    cudaGetSymbolAddress((void**)&wtlo, g_wtlo);
    cudaGetSymbolAddress((void**)&qhi, g_qhi);
    cudaGetSymbolAddress((void**)&qlo, g_qlo);
    cudaGetSymbolAddress((void**)&khi, g_khi);
    cudaGetSymbolAddress((void**)&klo, g_klo);
    cudaGetSymbolAddress((void**)&v, g_v);
    cudaGetSymbolAddress((void**)&scores, g_scores);
    cudaGetSymbolAddress((void**)&inv, g_inv);

    cudaFuncSetAttribute(gemm_hmma_kernel,
                         cudaFuncAttributeMaxDynamicSharedMemorySize, GEMM_SMEM);

    // 1. (x + pos) -> bf16 hi/lo split
    {
        int n4 = BT * DD / 4;
        add_split_kernel<<<(n4 + 255) / 256, 256>>>(x, pos, ahi, alo);
    }

    // 2. weight transpose + split (x3)
    {
        dim3 blk(32, 8);
        dim3 grid(DD / 32, DD / 32);
        for (int i = 0; i < 3; i++)
            wsplit_kernel<<<grid, blk>>>(W[i], wthi + (size_t)i * DD * DD,
                                         wtlo + (size_t)i * DD * DD);
    }

    // 3. merged q/k/v projections (A-tile L2 reuse: z folded into grid.x)
    {
        dim3 grid(24, BT / G_BM);
        gemm_hmma_kernel<<<grid, 512, GEMM_SMEM>>>(
            ahi, alo, wthi, wtlo, qhi, qlo, khi, klo, v);
    }

    // 4. raw masked scores via HMMA (upper-triangular tiles only)
    {
        dim3 grid(TT / 64, TT / 64, HB);
        scores_hmma_kernel<<<grid, 256>>>(qhi, qlo, khi, klo, scores);
    }

    // 5. per-(t,s) exp-sum over bh -> inv
    expsum_kernel<<<TS / 256, 256>>>(scores, inv);

    // 6. output via HMMA (split probs & V)
    {
        dim3 grid(TT / 64, HB);
        out_hmma_kernel<<<grid, 256>>>(scores, inv, v, out);
    }
}

// round 7
// speedup vs baseline: 2.5070x; 1.0233x over previous
#include <cuda_runtime.h>
#include <cuda_bf16.h>
#include <math.h>
#include <stdint.h>

// Problem constants
#define BB   64
#define TT   256
#define DD   1024
#define HH   16
#define DH   64
#define BT   (BB*TT)      // 16384
#define HB   (HH*BB)      // 1024
#define TS   (TT*TT)      // 65536

#define UNIF (1.0f / 1024.0f)   // exactly representable in bf16

// ---------------------------------------------------------------------------
// Scratch (__device__ globals; no allocation allowed)
// ---------------------------------------------------------------------------
__device__ __nv_bfloat16 g_ahi[BT * DD];        // 32 MB
__device__ __nv_bfloat16 g_alo[BT * DD];        // 32 MB
__device__ __nv_bfloat16 g_wthi[3][DD * DD];    // 2 MB x3  (transposed: [n][k])
__device__ __nv_bfloat16 g_wtlo[3][DD * DD];    // 2 MB x3
__device__ __nv_bfloat16 g_qhi[BT * DD];        // 32 MB
__device__ __nv_bfloat16 g_qlo[BT * DD];        // 32 MB
__device__ __nv_bfloat16 g_khi[BT * DD];        // 32 MB
__device__ __nv_bfloat16 g_klo[BT * DD];        // 32 MB
__device__ float g_v[BT * DD];                  // 64 MB
__device__ float g_scores[(size_t)HB * TS];     // 256 MB (raw scores, s>t valid)
__device__ float g_inv[TS];                     // 256 KB

// ---------------------------------------------------------------------------
// helpers
// ---------------------------------------------------------------------------
__device__ __forceinline__ uint32_t smem_u32(const void* p) {
    uint32_t a;
    asm("{ .reg .u64 t; cvta.to.shared.u64 t, %1; cvt.u32.u64 %0, t; }" : "=r"(a) : "l"(p));
    return a;
}
__device__ __forceinline__ void ldsm4(uint32_t* r, uint32_t a) {
    asm volatile("ldmatrix.sync.aligned.m8n8.x4.shared.b16 {%0,%1,%2,%3}, [%4];"
                 : "=r"(r[0]), "=r"(r[1]), "=r"(r[2]), "=r"(r[3]) : "r"(a));
}
__device__ __forceinline__ void mma16816(float* c, const uint32_t* a, const uint32_t* b) {
    asm volatile(
        "mma.sync.aligned.m16n8k16.row.col.f32.bf16.bf16.f32 "
        "{%0,%1,%2,%3}, {%4,%5,%6,%7}, {%8,%9}, {%0,%1,%2,%3};"
        : "+f"(c[0]), "+f"(c[1]), "+f"(c[2]), "+f"(c[3])
        : "r"(a[0]), "r"(a[1]), "r"(a[2]), "r"(a[3]), "r"(b[0]), "r"(b[1]));
}
#define CP16(sa, gp) \
    asm volatile("cp.async.cg.shared.global [%0], [%1], 16;" :: "r"(sa), "l"(gp))
#define CP_COMMIT() asm volatile("cp.async.commit_group;" ::: "memory")
#define CP_WAIT(n)  asm volatile("cp.async.wait_group %0;" :: "n"(n) : "memory")

__device__ __forceinline__ void split_bf16(float a, __nv_bfloat16& h, __nv_bfloat16& l) {
    h = __float2bfloat16_rn(a);
    l = __float2bfloat16_rn(a - __bfloat162float(h));
}

// ---------------------------------------------------------------------------
// Kernel 1: (x + pos) -> split into bf16 hi/lo
// ---------------------------------------------------------------------------
__global__ void add_split_kernel(const float* __restrict__ x,
                                 const float* __restrict__ pos,
                                 __nv_bfloat16* __restrict__ ahi,
                                 __nv_bfloat16* __restrict__ alo) {
    int i4 = blockIdx.x * blockDim.x + threadIdx.x;
    int n4 = BT * DD / 4;
    if (i4 >= n4) return;
    int td4 = i4 % (TT * DD / 4);
    float4 xv = ((const float4*)x)[i4];
    float4 pv = ((const float4*)pos)[td4];
    float a[4] = {xv.x + pv.x, xv.y + pv.y, xv.z + pv.z, xv.w + pv.w};
    __nv_bfloat16 hi[4], lo[4];
#pragma unroll
    for (int j = 0; j < 4; j++) split_bf16(a[j], hi[j], lo[j]);
    __nv_bfloat162 h0; h0.x = hi[0]; h0.y = hi[1];
    __nv_bfloat162 h1; h1.x = hi[2]; h1.y = hi[3];
    __nv_bfloat162 l0; l0.x = lo[0]; l0.y = lo[1];
    __nv_bfloat162 l1; l1.x = lo[2]; l1.y = lo[3];
    ((__nv_bfloat162*)ahi)[i4 * 2 + 0] = h0;
    ((__nv_bfloat162*)ahi)[i4 * 2 + 1] = h1;
    ((__nv_bfloat162*)alo)[i4 * 2 + 0] = l0;
    ((__nv_bfloat162*)alo)[i4 * 2 + 1] = l1;
}

// ---------------------------------------------------------------------------
// Kernel 2: weight transpose + split:  Wt_hi/lo[n][k] = split(W[k][n])
// ---------------------------------------------------------------------------
__global__ void wsplit_kernel(const float* __restrict__ W,
                              __nv_bfloat16* __restrict__ thi,
                              __nv_bfloat16* __restrict__ tlo) {
    __shared__ float tile[32][33];
    int k0 = blockIdx.x * 32;
    int n0 = blockIdx.y * 32;
    int tx = threadIdx.x;
    int ty = threadIdx.y;
#pragma unroll
    for (int i = 0; i < 32; i += 8)
        tile[ty + i][tx] = W[(size_t)(k0 + ty + i) * DD + n0 + tx];
    __syncthreads();
#pragma unroll
    for (int i = 0; i < 32; i += 8) {
        float v = tile[tx][ty + i];
        __nv_bfloat16 hi, lo;
        split_bf16(v, hi, lo);
        thi[(size_t)(n0 + ty + i) * DD + k0 + tx] = hi;
        tlo[(size_t)(n0 + ty + i) * DD + k0 + tx] = lo;
    }
}

// ---------------------------------------------------------------------------
// Kernel 3: merged HMMA projection GEMM, 128x256 CTA tile, 32x64 warp tile,
// 3-stage cp.async pipeline. grid.x = z*4 + ncol (z: Wq/Wk/Wv).
// z<2: epilogue writes bf16 hi/lo split (q,k).  z==2: fp32 (v).
// ---------------------------------------------------------------------------
#define G_BM 128
#define G_BN 256
#define G_BK 32
#define G_NCH (DD / G_BK)        // 32
#define G_RS 40                   // smem row stride in halfs (80 B)
#define OFF_AHI 0
#define OFF_ALO (G_BM * G_RS * 2)                 // 10240
#define OFF_BHI (2 * G_BM * G_RS * 2)             // 20480
#define OFF_BLO (OFF_BHI + G_BN * G_RS * 2)       // 40960
#define G_STAGE (OFF_BLO + G_BN * G_RS * 2)       // 61440
#define G_NSTAGE 3
#define GEMM_SMEM (G_NSTAGE * G_STAGE)            // 184320

__global__ __launch_bounds__(512) void gemm_hmma_kernel(
    const __nv_bfloat16* __restrict__ Ahi, const __nv_bfloat16* __restrict__ Alo,
    const __nv_bfloat16* __restrict__ Wthi, const __nv_bfloat16* __restrict__ Wtlo,
    __nv_bfloat16* __restrict__ Qhi, __nv_bfloat16* __restrict__ Qlo,
    __nv_bfloat16* __restrict__ Khi, __nv_bfloat16* __restrict__ Klo,
    float* __restrict__ V)
{
    extern __shared__ char smem[];
    const uint32_t sb = smem_u32(smem);
    const int tid = threadIdx.x;
    const int lane = tid & 31;
    const int wid = tid >> 5;
    const int wm = wid & 3;        // 4 warp rows (32 each)
    const int wn = wid >> 2;       // 4 warp cols (64 each)
    const int z = blockIdx.x >> 2;
    const int brow = blockIdx.y * G_BM;
    const int bcol = (blockIdx.x & 3) * G_BN;

    const __nv_bfloat16* Bhi = Wthi + (size_t)z * DD * DD;
    const __nv_bfloat16* Blo = Wtlo + (size_t)z * DD * DD;

    // copy indexing
    const int acrow = tid >> 2;          // 0..127
    const int acseg = tid & 3;           // 4 x 16B segs (k32 = 64B)
    const uint32_t a_soff = (uint32_t)(acrow * (G_RS * 2) + acseg * 16);
    const size_t ga_base = (size_t)(brow + acrow) * DD + acseg * 8;

    float acc[2][8][4];
#pragma unroll
    for (int mt = 0; mt < 2; mt++)
#pragma unroll
        for (int nt = 0; nt < 8; nt++)
#pragma unroll
            for (int i = 0; i < 4; i++) acc[mt][nt][i] = 0.0f;

    // stage loader
    auto load_stage = [&](int ch, int stg) {
        uint32_t st = sb + stg * G_STAGE;
        size_t goff = (size_t)ch * G_BK;
        CP16(st + OFF_AHI + a_soff, Ahi + ga_base + goff);
        CP16(st + OFF_ALO + a_soff, Alo + ga_base + goff);
#pragma unroll
        for (int i = 0; i < 2; i++) {
            int idx = tid + i * 512;     // 0..1023
            int r = idx >> 2;            // 0..255
            int seg = idx & 3;
            uint32_t so = (uint32_t)(r * (G_RS * 2) + seg * 16);
            size_t gb = (size_t)(bcol + r) * DD + seg * 8 + goff;
            CP16(st + OFF_BHI + so, Bhi + gb);
            CP16(st + OFF_BLO + so, Blo + gb);
        }
        CP_COMMIT();
    };

    load_stage(0, 0);
    load_stage(1, 1);

    const int a_row = lane & 15;
    const int a_k8  = (lane >> 4) * 8;
    const int b_row = (lane & 7) + ((lane & 16) ? 8 : 0);
    const int b_k8  = (lane & 8) ? 8 : 0;

    for (int ch = 0; ch < G_NCH; ch++) {
        if (ch + 2 < G_NCH) {
            load_stage(ch + 2, (ch + 2) % G_NSTAGE);
            CP_WAIT(2);
        } else if (ch + 1 < G_NCH) {
            CP_WAIT(1);
        } else {
            CP_WAIT(0);
        }
        __syncthreads();

        const uint32_t st = sb + (ch % G_NSTAGE) * G_STAGE;
#pragma unroll
        for (int ks = 0; ks < 2; ks++) {
            uint32_t aH[2][4], aL[2][4];
#pragma unroll
            for (int mt = 0; mt < 2; mt++) {
                uint32_t ao = st + OFF_AHI +
                    (uint32_t)((wm * 32 + mt * 16 + a_row) * (G_RS * 2) +
                               (ks * 16 + a_k8) * 2);
                ldsm4(aH[mt], ao);
                ldsm4(aL[mt], ao + (OFF_ALO - OFF_AHI));
            }
#pragma unroll
            for (int ph = 0; ph < 2; ph++) {       // two n32 halves
                uint32_t bH[2][4], bL[2][4];
#pragma unroll
                for (int p = 0; p < 2; p++) {
                    uint32_t bo = st + OFF_BHI +
                        (uint32_t)((wn * 64 + (ph * 2 + p) * 16 + b_row) * (G_RS * 2) +
                                   (ks * 16 + b_k8) * 2);
                    ldsm4(bH[p], bo);
                    ldsm4(bL[p], bo + (OFF_BLO - OFF_BHI));
                }
#pragma unroll
                for (int mt = 0; mt < 2; mt++)
#pragma unroll
                    for (int nl = 0; nl < 4; nl++) {
                        const uint32_t* bhp = &bH[nl >> 1][(nl & 1) * 2];
                        const uint32_t* blp = &bL[nl >> 1][(nl & 1) * 2];
                        float* a = acc[mt][ph * 4 + nl];
                        mma16816(a, aH[mt], bhp);
                        mma16816(a, aH[mt], blp);
                        mma16816(a, aL[mt], bhp);
                    }
            }
        }
        __syncthreads();
    }

    __nv_bfloat16* Ohi = (z == 0) ? Qhi : Khi;
    __nv_bfloat16* Olo = (z == 0) ? Qlo : Klo;
#pragma unroll
    for (int mt = 0; mt < 2; mt++) {
        int row = brow + wm * 32 + mt * 16 + (lane >> 2);
#pragma unroll
        for (int nt = 0; nt < 8; nt++) {
            int col = bcol + wn * 64 + nt * 8 + (lane & 3) * 2;
            if (z == 2) {
                *(float2*)(V + (size_t)row * DD + col) =
                    make_float2(acc[mt][nt][0], acc[mt][nt][1]);
                *(float2*)(V + (size_t)(row + 8) * DD + col) =
                    make_float2(acc[mt][nt][2], acc[mt][nt][3]);
            } else {
#pragma unroll
                for (int half = 0; half < 2; half++) {
                    int r = row + half * 8;
                    __nv_bfloat16 h0, l0, h1, l1;
                    split_bf16(acc[mt][nt][half * 2 + 0], h0, l0);
                    split_bf16(acc[mt][nt][half * 2 + 1], h1, l1);
                    __nv_bfloat162 hp; hp.x = h0; hp.y = h1;
                    __nv_bfloat162 lp; lp.x = l0; lp.y = l1;
                    *(__nv_bfloat162*)(Ohi + (size_t)r * DD + col) = hp;
                    *(__nv_bfloat162*)(Olo + (size_t)r * DD + col) = lp;
                }
            }
        }
    }
}

// ---------------------------------------------------------------------------
// Kernel 4: HMMA scores. Unconditional vector stores (masked slots are
// garbage and provably never read).
// ---------------------------------------------------------------------------
#define SC_STR 72   // smem row stride in halfs (144B)

__global__ __launch_bounds__(256) void scores_hmma_kernel(
    const __nv_bfloat16* __restrict__ qhi, const __nv_bfloat16* __restrict__ qlo,
    const __nv_bfloat16* __restrict__ khi, const __nv_bfloat16* __restrict__ klo,
    float* __restrict__ scores)
{
    const int t0 = blockIdx.y * 64;
    const int s0 = blockIdx.x * 64;
    if (s0 < t0) return;   // fully masked tile
    const int bh = blockIdx.z;
    const int b = bh & (BB - 1);
    const int h = bh >> 6;

    __shared__ __nv_bfloat16 sm[4][64 * SC_STR];

    const int tid = threadIdx.x;
    const int lane = tid & 31;
    const int wid = tid >> 5;
    const int wm = wid & 3;
    const int wn = wid >> 2;

    const __nv_bfloat16* gsrc[4] = {qhi, qlo, khi, klo};
#pragma unroll
    for (int tz = 0; tz < 4; tz++) {
        const __nv_bfloat16* g = gsrc[tz];
        const int rowbase = (tz < 2) ? t0 : s0;
        uint32_t sbase = smem_u32(&sm[tz][0]);
#pragma unroll
        for (int i = 0; i < 2; i++) {
            int idx = tid + i * 256;
            int r = idx >> 3;
            int seg = idx & 7;
            uint32_t sa = sbase + (uint32_t)(r * SC_STR * 2 + seg * 16);
            const __nv_bfloat16* gp = g + (size_t)(b * TT + rowbase + r) * DD +
                                      h * DH + seg * 8;
            CP16(sa, gp);
        }
    }
    CP_COMMIT(); CP_WAIT(0);
    __syncthreads();

    const uint32_t qh_b = smem_u32(&sm[0][0]);
    const uint32_t ql_b = smem_u32(&sm[1][0]);
    const uint32_t kh_b = smem_u32(&sm[2][0]);
    const uint32_t kl_b = smem_u32(&sm[3][0]);

    const int a_row = lane & 15;
    const int a_k8  = (lane >> 4) * 8;
    const int b_row = (lane & 7) + ((lane & 16) ? 8 : 0);
    const int b_k8  = (lane & 8) ? 8 : 0;

    float acc[4][4];
#pragma unroll
    for (int nt = 0; nt < 4; nt++)
#pragma unroll
        for (int i = 0; i < 4; i++) acc[nt][i] = 0.0f;

#pragma unroll
    for (int ks = 0; ks < 4; ks++) {
        uint32_t aH[4], aL[4];
        uint32_t ao = (uint32_t)((wm * 16 + a_row) * SC_STR * 2 + (ks * 16 + a_k8) * 2);
        ldsm4(aH, qh_b + ao);
        ldsm4(aL, ql_b + ao);
        uint32_t bH[2][4], bL[2][4];
#pragma unroll
        for (int p = 0; p < 2; p++) {
            uint32_t bo = (uint32_t)((wn * 32 + p * 16 + b_row) * SC_STR * 2 +
                                     (ks * 16 + b_k8) * 2);
            ldsm4(bH[p], kh_b + bo);
            ldsm4(bL[p], kl_b + bo);
        }
#pragma unroll
        for (int nt = 0; nt < 4; nt++) {
            const uint32_t* bhp = &bH[nt >> 1][(nt & 1) * 2];
            const uint32_t* blp = &bL[nt >> 1][(nt & 1) * 2];
            mma16816(acc[nt], aH, bhp);
            mma16816(acc[nt], aH, blp);
            mma16816(acc[nt], aL, bhp);
        }
    }

    float* outp = scores + (size_t)bh * TS;
    const int row0 = t0 + wm * 16 + (lane >> 2);
#pragma unroll
    for (int nt = 0; nt < 4; nt++) {
        int col = s0 + wn * 32 + nt * 8 + (lane & 3) * 2;
#pragma unroll
        for (int half = 0; half < 2; half++) {
            int r = row0 + half * 8;
            *(float2*)(outp + r * TT + col) =
                make_float2(acc[nt][half * 2 + 0] * 0.0625f,
                            acc[nt][half * 2 + 1] * 0.0625f);
        }
    }
}

// ---------------------------------------------------------------------------
// Kernel 5: expsum over bh -> inv (unmasked columns only)
// ---------------------------------------------------------------------------
__global__ void expsum_kernel(const float* __restrict__ scores,
                              float* __restrict__ inv) {
    int ts = blockIdx.x * blockDim.x + threadIdx.x;
    if (ts >= TS) return;
    int t = ts >> 8;
    int s = ts & 255;
    if (s <= t) return;
    const float* p = scores + ts;
    float sum = 0.0f;
#pragma unroll 8
    for (int bh = 0; bh < HB; bh++) sum += __expf(p[bh * TS]);
    inv[ts] = 1.0f / sum;
}

// ---------------------------------------------------------------------------
// Kernel 6: out = probs @ v_ on HMMA (split-bf16 probs & V).
// ---------------------------------------------------------------------------
__global__ __launch_bounds__(256) void out_hmma_kernel(
    const float* __restrict__ scores,
    const float* __restrict__ inv,
    const float* __restrict__ v,
    float* __restrict__ out)
{
    const int bh = blockIdx.y;
    const int b = bh & (BB - 1);
    const int h = bh >> 6;
    const int t0 = blockIdx.x * 64;

    __shared__ __nv_bfloat16 Ph[64 * SC_STR];
    __shared__ __nv_bfloat16 Pl[64 * SC_STR];
    __shared__ __nv_bfloat16 Vh[64 * SC_STR];   // [d][s]
    __shared__ __nv_bfloat16 Vl[64 * SC_STR];

    const int tid = threadIdx.x;
    const int lane = tid & 31;
    const int wid = tid >> 5;
    const int wm = wid & 3;        // t 16-block
    const int wn = wid >> 2;       // d 32-block

    const float* sbase = scores + (size_t)bh * TS;
    const float* vbase = v + (size_t)b * TT * DD + h * DH;

    const uint32_t ph_b = smem_u32(Ph);
    const uint32_t pl_b = smem_u32(Pl);
    const uint32_t vh_b = smem_u32(Vh);
    const uint32_t vl_b = smem_u32(Vl);

    const int a_row = lane & 15;
    const int a_k8  = (lane >> 4) * 8;
    const int b_row = (lane & 7) + ((lane & 16) ? 8 : 0);
    const int b_k8  = (lane & 8) ? 8 : 0;

    float acc[4][4];
#pragma unroll
    for (int nt = 0; nt < 4; nt++)
#pragma unroll
        for (int i = 0; i < 4; i++) acc[nt][i] = 0.0f;

    for (int s0 = 0; s0 < TT; s0 += 64) {
        const bool full_masked = (s0 + 64 <= t0);

        // V tile -> transposed split  Vt[d][s]
#pragma unroll
        for (int i = 0; i < 4; i++) {
            int idx = tid + i * 256;
            int s = idx >> 4;
            int d4 = (idx & 15) * 4;
            float4 vv = *(const float4*)(vbase + (size_t)(s0 + s) * DD + d4);
            float vals[4] = {vv.x, vv.y, vv.z, vv.w};
#pragma unroll
            for (int j = 0; j < 4; j++) {
                __nv_bfloat16 hi, lo;
                split_bf16(vals[j], hi, lo);
                Vh[(d4 + j) * SC_STR + s] = hi;
                Vl[(d4 + j) * SC_STR + s] = lo;
            }
        }

        // Ps tile
        if (full_masked) {
            const __nv_bfloat16 uh = __float2bfloat16_rn(UNIF);
#pragma unroll
            for (int i = 0; i < 4; i++) {
                int idx = tid + i * 256;
                int r = idx >> 4;
                int c4 = (idx & 15) * 4;
#pragma unroll
                for (int j = 0; j < 4; j++)
                    Ph[r * SC_STR + c4 + j] = uh;
            }
        } else {
#pragma unroll
            for (int i = 0; i < 4; i++) {
                int idx = tid + i * 256;
                int r = idx >> 4;
                int c4 = (idx & 15) * 4;
                int t = t0 + r;
                float4 sc = *(const float4*)(sbase + t * TT + s0 + c4);
                float4 iv = *(const float4*)(inv + t * TT + s0 + c4);
                float scs[4] = {sc.x, sc.y, sc.z, sc.w};
                float ivs[4] = {iv.x, iv.y, iv.z, iv.w};
#pragma unroll
                for (int j = 0; j < 4; j++) {
                    int s = s0 + c4 + j;
                    float w = (s <= t) ? UNIF : __expf(scs[j]) * ivs[j];
                    __nv_bfloat16 hi, lo;
                    split_bf16(w, hi, lo);
                    Ph[r * SC_STR + c4 + j] = hi;
                    Pl[r * SC_STR + c4 + j] = lo;
                }
            }
        }
        __syncthreads();

#pragma unroll
        for (int ks = 0; ks < 4; ks++) {
            uint32_t aH[4], aL[4];
            uint32_t ao = (uint32_t)((wm * 16 + a_row) * SC_STR * 2 + (ks * 16 + a_k8) * 2);
            ldsm4(aH, ph_b + ao);
            if (!full_masked) ldsm4(aL, pl_b + ao);
            uint32_t bH[2][4], bL[2][4];
#pragma unroll
            for (int p = 0; p < 2; p++) {
                uint32_t bo = (uint32_t)((wn * 32 + p * 16 + b_row) * SC_STR * 2 +
                                         (ks * 16 + b_k8) * 2);
                ldsm4(bH[p], vh_b + bo);
                ldsm4(bL[p], vl_b + bo);
            }
#pragma unroll
            for (int nt = 0; nt < 4; nt++) {
                const uint32_t* bhp = &bH[nt >> 1][(nt & 1) * 2];
                const uint32_t* blp = &bL[nt >> 1][(nt & 1) * 2];
                mma16816(acc[nt], aH, bhp);
                mma16816(acc[nt], aH, blp);
                if (!full_masked) mma16816(acc[nt], aL, bhp);
            }
        }
        __syncthreads();
    }

    const int row0 = t0 + wm * 16 + (lane >> 2);
#pragma unroll
    for (int nt = 0; nt < 4; nt++) {
        int col = wn * 32 + nt * 8 + (lane & 3) * 2;
#pragma unroll
        for (int half = 0; half < 2; half++) {
            int r = row0 + half * 8;
            *(float2*)(out + (size_t)(b * TT + r) * DD + h * DH + col) =
                make_float2(acc[nt][half * 2 + 0], acc[nt][half * 2 + 1]);
        }
    }
}

// ---------------------------------------------------------------------------
// Launch
// ---------------------------------------------------------------------------
extern "C" void kernel_launch(void* const* d_in, const int* in_sizes, int n_in,
                              void* d_out, int out_size) {
    const float* x   = (const float*)d_in[0];
    const float* pos = (const float*)d_in[1];
    const float* W[3] = {(const float*)d_in[2], (const float*)d_in[3], (const float*)d_in[4]};
    float* out = (float*)d_out;

    __nv_bfloat16 *ahi, *alo, *wthi, *wtlo, *qhi, *qlo, *khi, *klo;
    float *v, *scores, *inv;
    cudaGetSymbolAddress((void**)&ahi, g_ahi);
    cudaGetSymbolAddress((void**)&alo, g_alo);
    cudaGetSymbolAddress((void**)&wthi, g_wthi);
    cudaGetSymbolAddress((void**)&wtlo, g_wtlo);
    cudaGetSymbolAddress((void**)&qhi, g_qhi);
    cudaGetSymbolAddress((void**)&qlo, g_qlo);
    cudaGetSymbolAddress((void**)&khi, g_khi);
    cudaGetSymbolAddress((void**)&klo, g_klo);
    cudaGetSymbolAddress((void**)&v, g_v);
    cudaGetSymbolAddress((void**)&scores, g_scores);
    cudaGetSymbolAddress((void**)&inv, g_inv);

    cudaFuncSetAttribute(gemm_hmma_kernel,
                         cudaFuncAttributeMaxDynamicSharedMemorySize, GEMM_SMEM);

    // 1. (x + pos) -> bf16 hi/lo split
    {
        int n4 = BT * DD / 4;
        add_split_kernel<<<(n4 + 255) / 256, 256>>>(x, pos, ahi, alo);
    }

    // 2. weight transpose + split (x3)
    {
        dim3 blk(32, 8);
        dim3 grid(DD / 32, DD / 32);
        for (int i = 0; i < 3; i++)
            wsplit_kernel<<<grid, blk>>>(W[i], wthi + (size_t)i * DD * DD,
                                         wtlo + (size_t)i * DD * DD);
    }

    // 3. merged q/k/v projections (128x256 tiles, 3-stage pipeline)
    {
        dim3 grid(12, BT / G_BM);   // x = z*4 + ncol
        gemm_hmma_kernel<<<grid, 512, GEMM_SMEM>>>(
            ahi, alo, wthi, wtlo, qhi, qlo, khi, klo, v);
    }

    // 4. raw masked scores via HMMA (upper-triangular tiles only)
    {
        dim3 grid(TT / 64, TT / 64, HB);
        scores_hmma_kernel<<<grid, 256>>>(qhi, qlo, khi, klo, scores);
    }

    // 5. per-(t,s) exp-sum over bh -> inv
    expsum_kernel<<<TS / 256, 256>>>(scores, inv);

    // 6. output via HMMA (split probs & V)
    {
        dim3 grid(TT / 64, HB);
        out_hmma_kernel<<<grid, 256>>>(scores, inv, v, out);
    }
}